// round 7
// baseline (speedup 1.0000x reference)
#include <cuda_runtime.h>
#include <cuda_fp16.h>
#include <math.h>
#include <stdint.h>

#define BSZ 8
#define NQ 900
#define DD 256
#define KK 10
#define ROWS (BSZ*NQ)        /* 7200  */
#define FMAX (ROWS*KK)       /* 72000 */
#define WDIM 512

// ---------------- scratch (static __device__ arrays; no allocation) ----------
__device__ float4 g_pm[FMAX];
__device__ float  g_w[FMAX];
__device__ float  g_oval[FMAX];
__device__ float  g_mkval[FMAX];
__device__ __half g_Wv[(size_t)FMAX*WDIM];   // wave features, fp16
__device__ __half g_H[(size_t)FMAX*DD];      // relu(features@W3+b3), fp16
__device__ float  g_feat[(size_t)FMAX*DD];   // H@W4+b4, fp32 (feeds max-reduce)
__device__ int    g_rowbase[ROWS];
__device__ int    g_rowcnt[ROWS];
__device__ __half g_T1[(size_t)ROWS*DD];     // relu(tgt@W1+b1), fp16
__device__ __half g_Z[(size_t)ROWS*DD];      // cur*neg+agg, fp16
__device__ float  g_agg[(size_t)ROWS*DD];
__device__ float  g_s64[DD];
__device__ int    g_count;
// transposed weights, [N][K] K-major rows, fp16
__device__ __half g_W3T[DD*WDIM];
__device__ __half g_W1T[DD*DD];
__device__ __half g_W2T[DD*DD];
__device__ __half g_W4T[DD*DD];
__device__ __half g_W5T[DD*DD];

__device__ __forceinline__ void mma_f16(float* c, const uint32_t* a, const uint32_t* b) {
    asm volatile(
        "mma.sync.aligned.m16n8k16.row.col.f32.f16.f16.f32 "
        "{%0,%1,%2,%3}, {%4,%5,%6,%7}, {%8,%9}, {%0,%1,%2,%3};"
        : "+f"(c[0]), "+f"(c[1]), "+f"(c[2]), "+f"(c[3])
        : "r"(a[0]), "r"(a[1]), "r"(a[2]), "r"(a[3]), "r"(b[0]), "r"(b[1]));
}
__device__ __forceinline__ void ldsm4(uint32_t* r, uint32_t addr) {
    asm volatile("ldmatrix.sync.aligned.m8n8.x4.shared.b16 {%0,%1,%2,%3}, [%4];"
        : "=r"(r[0]), "=r"(r[1]), "=r"(r[2]), "=r"(r[3]) : "r"(addr));
}
__device__ __forceinline__ uint32_t smem_u32(const void* p) {
    uint32_t a;
    asm("{ .reg .u64 t; cvta.to.shared.u64 t, %1; cvt.u32.u64 %0, t; }" : "=r"(a) : "l"(p));
    return a;
}
__device__ __forceinline__ uint32_t packh2(float a, float b) {
    __half2 h = __floats2half2_rn(a, b);
    return *(uint32_t*)&h;
}

// ---------------- prep: transpose weights (to fp16) + s64 + counter ---------
__global__ void k_prep(const float* __restrict__ W1, const float* __restrict__ W2,
                       const float* __restrict__ W3, const float* __restrict__ W4,
                       const float* __restrict__ W5) {
    int idx = blockIdx.x * 256 + threadIdx.x;
    if (idx < 131072) {                       // W3T [256][512] from W3[64+k][n]
        int n = idx >> 9, k = idx & 511;
        g_W3T[idx] = __float2half(W3[(size_t)(64 + k) * DD + n]);
    } else {
        int r = idx - 131072;
        int m = r >> 16, e = r & 65535;
        int n = e >> 8, k = e & 255;
        if      (m == 0) g_W1T[e] = __float2half(W1[(size_t)k*DD + n]);
        else if (m == 1) g_W2T[e] = __float2half(W2[(size_t)k*DD + n]);
        else if (m == 2) g_W4T[e] = __float2half(W4[(size_t)k*DD + n]);
        else             g_W5T[e] = __float2half(W5[(size_t)k*DD + n]);
    }
}
__global__ void k_init(const float* __restrict__ W3) {
    int n = threadIdx.x;
    float s = 0.f;
    #pragma unroll 8
    for (int r = 0; r < 64; r++) s += W3[r*DD + n];
    g_s64[n] = s;
    if (n == 0) g_count = 0;
}

// ---------------- top-K: one warp per row, register-resident ----------------
#define NU 29   /* ceil(900/32) */
__global__ __launch_bounds__(256)
void k_topk(const float* __restrict__ ious,
            const float* __restrict__ gmask,
            const float* __restrict__ bboxes) {
    int wid = threadIdx.x >> 5, lid = threadIdx.x & 31;
    int r = blockIdx.x * 8 + wid;
    if (r >= ROWS) return;
    int b = r / NQ, i = r % NQ;
    const float* Mrow = gmask + b*NQ;
    float neg_i = 1.0f - Mrow[i];
    if (neg_i == 0.0f) {
        if (lid == 0) { g_rowbase[r] = 0; g_rowcnt[r] = 0; }
        return;
    }
    const float* irow = ious + (size_t)r * NQ;
    float ov[NU];
    #pragma unroll
    for (int u = 0; u < NU; u++) {
        int j = lid + u*32;
        ov[u] = (j < NQ) ? irow[j] * Mrow[j] * neg_i : -3.4e38f;
    }
    float kv[KK]; int ki[KK];
    float lastv = 3.5e38f; int lasti = -1;
    #pragma unroll
    for (int t = 0; t < KK; t++) {
        float lv = -3.4e38f; int li = NQ;
        #pragma unroll
        for (int u = 0; u < NU; u++) {
            int j = lid + u*32;
            float v = ov[u];
            bool inc = (v < lastv) || (v == lastv && j > lasti);
            if (inc && (v > lv || (v == lv && j < li))) { lv = v; li = j; }
        }
        #pragma unroll
        for (int off = 16; off > 0; off >>= 1) {
            float vv = __shfl_xor_sync(0xffffffffu, lv, off);
            int   ii = __shfl_xor_sync(0xffffffffu, li, off);
            if (vv > lv || (vv == lv && ii < li)) { lv = vv; li = ii; }
        }
        kv[t] = lv; ki[t] = li;
        lastv = lv; lasti = li;
    }
    if (lid == 0) {
        float mkv[KK];
        int cnt = 0;
        #pragma unroll
        for (int t = 0; t < KK; t++) {
            float nmk = Mrow[ki[t]];
            float mk  = (kv[t] >= 0.4f) ? nmk : 0.0f;
            mkv[t] = mk;
            if (mk != 0.0f) cnt++;
        }
        int base = (cnt > 0) ? atomicAdd(&g_count, cnt) : 0;
        g_rowbase[r] = base; g_rowcnt[r] = cnt;

        const float* cb = bboxes + (size_t)r * 4;
        float ccx = 0.5f*(cb[0]+cb[2]), ccy = 0.5f*(cb[1]+cb[3]);
        float cw = cb[2]-cb[0], ch = cb[3]-cb[1];
        int s = 0;
        #pragma unroll
        for (int t = 0; t < KK; t++) {
            if (mkv[t] == 0.0f) continue;
            const float* nb = bboxes + (size_t)(b*NQ + ki[t]) * 4;
            float dcx = 0.5f*(nb[0]+nb[2]) - ccx;
            float dcy = 0.5f*(nb[1]+nb[3]) - ccy;
            float dw  = (nb[2]-nb[0]) - cw;
            float dh  = (nb[3]-nb[1]) - ch;
            float4 pm;
            pm.x = logf(fmaxf(fabsf(dcx), 1e-7f));
            pm.y = logf(fmaxf(fabsf(dcy), 1e-7f));
            pm.z = logf(fmaxf(fabsf(dw ), 1e-7f));
            pm.w = logf(fmaxf(fabsf(dh ), 1e-7f));
            g_pm[base+s]    = pm;
            g_w[base+s]     = neg_i * Mrow[ki[t]] * mkv[t];
            g_oval[base+s]  = kv[t] * mkv[t];
            g_mkval[base+s] = mkv[t];
            s++;
        }
    }
}

// ---------------- wave generation (fp16, pairs share one trig) --------------
// j = a*256 + sf*128 + f; value = (sf?cos:sin)(coef[f>>1]*pm[2a+sf]) * w
// thread -> (entry, seg of 16 j's); seg = a*16 + sf*8 + (f0/16)
__global__ __launch_bounds__(256) void k_wave() {
    int idx = blockIdx.x * 256 + threadIdx.x;
    int e = idx >> 5;
    if (e >= g_count) return;
    int seg = idx & 31;
    float4 pm = g_pm[e];
    float w = g_w[e];
    int a = seg >> 4, sf = (seg >> 3) & 1;
    int f2base = (seg & 7) * 8;
    float p = ((const float*)&pm)[2*a + sf];
    uint32_t h[8];
    #pragma unroll
    for (int u = 0; u < 8; u++) {
        float coef = 6.2831853071795865f *
                     exp2f(-(float)(f2base + u) * (13.287712379549450f/64.f));
        float ang = coef * p;
        float v = (sf ? __cosf(ang) : __sinf(ang)) * w;
        h[u] = packh2(v, v);   // f even/odd pair -> identical values
    }
    uint4* dst = (uint4*)(g_Wv + (size_t)e*WDIM + seg*16);
    dst[0] = make_uint4(h[0], h[1], h[2], h[3]);
    dst[1] = make_uint4(h[4], h[5], h[6], h[7]);
}

// ---------------- fp16 mma.sync GEMM: 128x128 tile, BK=32, double-buffered --
enum { MG1 = 0, MG2 = 1, MC1 = 2, MC2 = 3, MOUT = 4 };
#define BM 128
#define BN 128
#define BK 32     /* fp16 k-elements per chunk */
#define PADH 40   /* padded row stride in fp16 units; 80B -> conflict-free ldmatrix */

template<int MODE>
__global__ __launch_bounds__(256)
void gemm_mma(const float* __restrict__ Afe,   // external fp32 A (MC1: tgt)
              const float* __restrict__ bias,
              const float* __restrict__ gmask,
              float* __restrict__ Cfe,         // external fp32 C (MOUT: out)
              int Mext) {
    constexpr bool AH = (MODE != MC1);                           // A is fp16
    constexpr bool OH = (MODE == MG1 || MODE == MC1 || MODE == MC2); // C is fp16

    __shared__ __align__(16) __half Ash[2][BM*PADH];
    __shared__ __align__(16) __half Bsh[2][BN*PADH];
    __shared__ float bias_s[BN];
    __shared__ float s64_s[BN];

    const int Kd = (MODE == MG1) ? WDIM : DD;
    int M = (MODE == MG1 || MODE == MG2) ? g_count : Mext;
    int m0 = blockIdx.x * BM;
    if (m0 >= M) return;
    int n0 = blockIdx.y * BN;

    const __half* Ahp = nullptr;
    const float*  Afp = nullptr;
    const __half* BT;
    __half* Chp = nullptr;
    float*  Cfp = nullptr;
    if (MODE == MG1)      { Ahp = g_Wv; BT = g_W3T; Chp = g_H; }
    else if (MODE == MG2) { Ahp = g_H;  BT = g_W4T; Cfp = g_feat; }
    else if (MODE == MC1) { Afp = Afe;  BT = g_W1T; Chp = g_T1; }
    else if (MODE == MC2) { Ahp = g_T1; BT = g_W2T; Chp = g_Z; }
    else                  { Ahp = g_Z;  BT = g_W5T; Cfp = Cfe; }

    int tid = threadIdx.x, wid = tid >> 5, lid = tid & 31;
    int gid = lid >> 2, ti = lid & 3;
    int warpM = wid & 1, warpN = wid >> 1;

    if (tid < BN) {
        bias_s[tid] = bias[n0 + tid];
        if (MODE == MG1) s64_s[tid] = g_s64[n0 + tid];
    }
    __syncthreads();

    // staging: thread -> row tid>>1 (0..127), half-chunk kh=(tid&1)*16 fp16
    int s_row = tid >> 1;
    int s_kh  = (tid & 1) * 16;
    uint32_t pa[8], pb[8];

    auto loadA = [&](int c) {
        int gr = m0 + s_row;
        if (AH) {
            uint4 v0 = make_uint4(0,0,0,0), v1 = v0;
            if (gr < M) {
                const uint4* ap = (const uint4*)(Ahp + (size_t)gr*Kd + c*BK + s_kh);
                v0 = ap[0]; v1 = ap[1];
            }
            pa[0]=v0.x; pa[1]=v0.y; pa[2]=v0.z; pa[3]=v0.w;
            pa[4]=v1.x; pa[5]=v1.y; pa[6]=v1.z; pa[7]=v1.w;
        } else {
            const float* ap = Afp + (size_t)gr*Kd + c*BK + s_kh;
            #pragma unroll
            for (int q = 0; q < 4; q++) {
                float4 fv = make_float4(0.f,0.f,0.f,0.f);
                if (gr < M) fv = *(const float4*)(ap + q*4);
                pa[q*2+0] = packh2(fv.x, fv.y);
                pa[q*2+1] = packh2(fv.z, fv.w);
            }
        }
    };
    auto loadB = [&](int c) {
        const uint4* bp = (const uint4*)(BT + (size_t)(n0 + s_row)*Kd + c*BK + s_kh);
        uint4 v0 = bp[0], v1 = bp[1];
        pb[0]=v0.x; pb[1]=v0.y; pb[2]=v0.z; pb[3]=v0.w;
        pb[4]=v1.x; pb[5]=v1.y; pb[6]=v1.z; pb[7]=v1.w;
    };
    auto store = [&](int buf) {
        uint32_t* ad = (uint32_t*)&Ash[buf][s_row*PADH + s_kh];
        uint32_t* bd = (uint32_t*)&Bsh[buf][s_row*PADH + s_kh];
        *(uint4*)(ad)     = make_uint4(pa[0], pa[1], pa[2], pa[3]);
        *(uint4*)(ad + 4) = make_uint4(pa[4], pa[5], pa[6], pa[7]);
        *(uint4*)(bd)     = make_uint4(pb[0], pb[1], pb[2], pb[3]);
        *(uint4*)(bd + 4) = make_uint4(pb[4], pb[5], pb[6], pb[7]);
    };

    // ldmatrix per-lane addresses (bytes): row = lid&15, k-octet = (lid>>4)*8 fp16
    uint32_t As_b = smem_u32(&Ash[0][0]);
    uint32_t Bs_b = smem_u32(&Bsh[0][0]);
    const uint32_t ABYTES = BM*PADH*2u;
    const uint32_t BBYTES = BN*PADH*2u;
    int l16 = lid & 15, lk = (lid >> 4) * 8;
    uint32_t aaddr = As_b + (uint32_t)((warpM*64 + l16) * PADH + lk) * 2u;
    uint32_t baddr = Bs_b + (uint32_t)((warpN*32 + l16) * PADH + lk) * 2u;

    float acc[4][4][4];
    #pragma unroll
    for (int m = 0; m < 4; m++)
        #pragma unroll
        for (int n = 0; n < 4; n++)
            #pragma unroll
            for (int q = 0; q < 4; q++) acc[m][n][q] = 0.f;

    loadA(0); loadB(0);
    store(0);
    __syncthreads();

    const int nc = Kd / BK;
    for (int c = 0; c < nc; c++) {
        int buf = c & 1;
        bool pf = (c + 1 < nc);
        if (pf) { loadA(c+1); loadB(c+1); store(buf ^ 1); }
        uint32_t abase = aaddr + buf * ABYTES;
        uint32_t bbase = baddr + buf * BBYTES;
        #pragma unroll
        for (int kb = 0; kb < BK; kb += 16) {
            uint32_t af[4][4], bq[2][4];
            #pragma unroll
            for (int m = 0; m < 4; m++)
                ldsm4(af[m], abase + (uint32_t)((m*16*PADH + kb) * 2));
            #pragma unroll
            for (int g = 0; g < 2; g++)
                ldsm4(bq[g], bbase + (uint32_t)((g*16*PADH + kb) * 2));
            #pragma unroll
            for (int m = 0; m < 4; m++) {
                #pragma unroll
                for (int n = 0; n < 4; n++) {
                    uint32_t bfr[2] = { bq[n>>1][n&1], bq[n>>1][(n&1)+2] };
                    mma_f16(acc[m][n], af[m], bfr);
                }
            }
        }
        __syncthreads();
    }

    // ---- epilogue ----
    #pragma unroll
    for (int m = 0; m < 4; m++) {
        int r0 = m0 + warpM*64 + m*16 + gid;
        int r1 = r0 + 8;
        bool ok0 = r0 < M, ok1 = r1 < M;
        float ovl0 = 0.f, ovl1 = 0.f, ng0 = 1.f, ng1 = 1.f;
        if (MODE == MG1) {
            if (ok0) ovl0 = g_oval[r0];
            if (ok1) ovl1 = g_oval[r1];
        }
        if (MODE == MC2 || MODE == MOUT) {
            if (ok0) ng0 = 1.f - gmask[r0];
            if (ok1) ng1 = 1.f - gmask[r1];
        }
        #pragma unroll
        for (int n = 0; n < 4; n++) {
            int lc = warpN*32 + n*8 + ti*2;
            int col = n0 + lc;
            float b0 = bias_s[lc], b1 = bias_s[lc+1];
            #pragma unroll
            for (int h = 0; h < 2; h++) {
                int row = h ? r1 : r0;
                bool ok = h ? ok1 : ok0;
                if (!ok) continue;
                float ovl = h ? ovl1 : ovl0;
                float ng  = h ? ng1  : ng0;
                float v0 = acc[m][n][h*2+0] + b0;
                float v1 = acc[m][n][h*2+1] + b1;
                if (MODE == MG1) {
                    v0 = fmaxf(v0 + ovl * s64_s[lc],   0.f);
                    v1 = fmaxf(v1 + ovl * s64_s[lc+1], 0.f);
                } else if (MODE == MC1) {
                    v0 = fmaxf(v0, 0.f); v1 = fmaxf(v1, 0.f);
                } else if (MODE == MC2) {
                    const float* ar = g_agg + (size_t)row*DD + col;
                    v0 = v0 * ng + ar[0];
                    v1 = v1 * ng + ar[1];
                } else if (MODE == MOUT) {
                    v0 = fmaxf(v0, 0.f) * ng; v1 = fmaxf(v1, 0.f) * ng;
                }
                if (OH) {
                    __half2 o = __floats2half2_rn(v0, v1);
                    *(__half2*)(Chp + (size_t)row*DD + col) = o;
                } else {
                    *(float2*)(Cfp + (size_t)row*DD + col) = make_float2(v0, v1);
                }
            }
        }
    }
}

// ---------------- masked max over K neighbors -------------------------------
__global__ void k_reduce() {
    int r = blockIdx.x, d = threadIdx.x;
    int base = g_rowbase[r], cnt = g_rowcnt[r];
    float m = (cnt < KK) ? 0.0f : -3.4e38f;
    for (int e = 0; e < cnt; e++)
        m = fmaxf(m, g_mkval[base+e] * g_feat[(size_t)(base+e)*DD + d]);
    g_agg[(size_t)r*DD + d] = m;
}

// ---------------- launch ----------------------------------------------------
extern "C" void kernel_launch(void* const* d_in, const int* in_sizes, int n_in,
                              void* d_out, int out_size) {
    const float* tgt    = (const float*)d_in[0];
    const float* ious   = (const float*)d_in[1];
    const float* bboxes = (const float*)d_in[2];
    const float* gmask  = (const float*)d_in[3];
    const float* W1 = (const float*)d_in[4];  const float* b1 = (const float*)d_in[5];
    const float* W2 = (const float*)d_in[6];  const float* b2 = (const float*)d_in[7];
    const float* W3 = (const float*)d_in[8];  const float* b3 = (const float*)d_in[9];
    const float* W4 = (const float*)d_in[10]; const float* b4 = (const float*)d_in[11];
    const float* W5 = (const float*)d_in[12]; const float* b5 = (const float*)d_in[13];
    float* out = (float*)d_out;

    k_prep<<<1536, 256>>>(W1, W2, W3, W4, W5);
    k_init<<<1, 256>>>(W3);
    k_topk<<<(ROWS + 7) / 8, 256>>>(ious, gmask, bboxes);
    k_wave<<<(FMAX * 32) / 256, 256>>>();

    dim3 gdyn((FMAX + 127) / 128, 2);   // 563 x 2
    dim3 gfix((ROWS + 127) / 128, 2);   // 57 x 2

    gemm_mma<MG1><<<gdyn, 256>>>(nullptr, b3, nullptr, nullptr, 0);
    gemm_mma<MG2><<<gdyn, 256>>>(nullptr, b4, nullptr, nullptr, 0);
    k_reduce<<<ROWS, DD>>>();
    gemm_mma<MC1><<<gfix, 256>>>(tgt,     b1, nullptr, nullptr, ROWS);
    gemm_mma<MC2><<<gfix, 256>>>(nullptr, b2, gmask,  nullptr, ROWS);
    gemm_mma<MOUT><<<gfix, 256>>>(nullptr, b5, gmask, out,     ROWS);
}

// round 8
// speedup vs baseline: 1.0445x; 1.0445x over previous
#include <cuda_runtime.h>
#include <cuda_fp16.h>
#include <math.h>
#include <stdint.h>

#define BSZ 8
#define NQ 900
#define DD 256
#define KK 10
#define ROWS (BSZ*NQ)        /* 7200  */
#define FMAX (ROWS*KK)       /* 72000 */
#define WDIM 512

// ---------------- scratch (static __device__ arrays; no allocation) ----------
__device__ __align__(256) float4 g_pm[FMAX];
__device__ __align__(256) float  g_w[FMAX];
__device__ __align__(256) float  g_oval[FMAX];
__device__ __align__(256) float  g_mkval[FMAX];
__device__ __align__(256) __half g_H[(size_t)FMAX*DD];      // relu(feat@W3+b3), fp16
__device__ __align__(256) float  g_feat[(size_t)FMAX*DD];   // H@W4+b4, fp32
__device__ int    g_rowbase[ROWS];
__device__ int    g_rowcnt[ROWS];
__device__ __align__(256) __half g_T1[(size_t)ROWS*DD];
__device__ __align__(256) __half g_Z[(size_t)ROWS*DD];
__device__ __align__(256) float  g_agg[(size_t)ROWS*DD];
__device__ float  g_s64[DD];
__device__ int    g_count;
// transposed weights, [N][K] K-major rows, fp16
__device__ __align__(256) __half g_W3T[DD*WDIM];
__device__ __align__(256) __half g_W1T[DD*DD];
__device__ __align__(256) __half g_W2T[DD*DD];
__device__ __align__(256) __half g_W4T[DD*DD];
__device__ __align__(256) __half g_W5T[DD*DD];

__device__ __forceinline__ void mma_f16(float* c, const uint32_t* a, const uint32_t* b) {
    asm volatile(
        "mma.sync.aligned.m16n8k16.row.col.f32.f16.f16.f32 "
        "{%0,%1,%2,%3}, {%4,%5,%6,%7}, {%8,%9}, {%0,%1,%2,%3};"
        : "+f"(c[0]), "+f"(c[1]), "+f"(c[2]), "+f"(c[3])
        : "r"(a[0]), "r"(a[1]), "r"(a[2]), "r"(a[3]), "r"(b[0]), "r"(b[1]));
}
__device__ __forceinline__ void ldsm4(uint32_t* r, uint32_t addr) {
    asm volatile("ldmatrix.sync.aligned.m8n8.x4.shared.b16 {%0,%1,%2,%3}, [%4];"
        : "=r"(r[0]), "=r"(r[1]), "=r"(r[2]), "=r"(r[3]) : "r"(addr));
}
__device__ __forceinline__ uint32_t smem_u32(const void* p) {
    uint32_t a;
    asm("{ .reg .u64 t; cvta.to.shared.u64 t, %1; cvt.u32.u64 %0, t; }" : "=r"(a) : "l"(p));
    return a;
}
__device__ __forceinline__ uint32_t packh2(float a, float b) {
    __half2 h = __floats2half2_rn(a, b);
    return *(uint32_t*)&h;
}
#define CP16(dst, src) asm volatile("cp.async.cg.shared.global [%0], [%1], 16;" :: "r"(dst), "l"(src))
#define CP_COMMIT()    asm volatile("cp.async.commit_group;" ::: "memory")
#define CP_WAIT0()     asm volatile("cp.async.wait_group 0;" ::: "memory")

// ---------------- prep: transpose weights (to fp16) + s64 + counter ---------
__global__ void k_prep(const float* __restrict__ W1, const float* __restrict__ W2,
                       const float* __restrict__ W3, const float* __restrict__ W4,
                       const float* __restrict__ W5) {
    int idx = blockIdx.x * 256 + threadIdx.x;
    if (idx < 131072) {                       // W3T [256][512] from W3[64+k][n]
        int n = idx >> 9, k = idx & 511;
        g_W3T[idx] = __float2half(W3[(size_t)(64 + k) * DD + n]);
    } else {
        int r = idx - 131072;
        int m = r >> 16, e = r & 65535;
        int n = e >> 8, k = e & 255;
        if      (m == 0) g_W1T[e] = __float2half(W1[(size_t)k*DD + n]);
        else if (m == 1) g_W2T[e] = __float2half(W2[(size_t)k*DD + n]);
        else if (m == 2) g_W4T[e] = __float2half(W4[(size_t)k*DD + n]);
        else             g_W5T[e] = __float2half(W5[(size_t)k*DD + n]);
    }
}
__global__ void k_init(const float* __restrict__ W3) {
    int n = threadIdx.x;
    float s = 0.f;
    #pragma unroll 8
    for (int r = 0; r < 64; r++) s += W3[r*DD + n];
    g_s64[n] = s;
    if (n == 0) g_count = 0;
}

// ---------------- top-K: one warp per row, register-resident ----------------
#define NU 29   /* ceil(900/32) */
__global__ __launch_bounds__(256)
void k_topk(const float* __restrict__ ious,
            const float* __restrict__ gmask,
            const float* __restrict__ bboxes) {
    int wid = threadIdx.x >> 5, lid = threadIdx.x & 31;
    int r = blockIdx.x * 8 + wid;
    if (r >= ROWS) return;
    int b = r / NQ, i = r % NQ;
    const float* Mrow = gmask + b*NQ;
    float neg_i = 1.0f - Mrow[i];
    if (neg_i == 0.0f) {
        if (lid == 0) { g_rowbase[r] = 0; g_rowcnt[r] = 0; }
        return;
    }
    const float* irow = ious + (size_t)r * NQ;
    float ov[NU];
    #pragma unroll
    for (int u = 0; u < NU; u++) {
        int j = lid + u*32;
        ov[u] = (j < NQ) ? irow[j] * Mrow[j] * neg_i : -3.4e38f;
    }
    float kv[KK]; int ki[KK];
    float lastv = 3.5e38f; int lasti = -1;
    #pragma unroll
    for (int t = 0; t < KK; t++) {
        float lv = -3.4e38f; int li = NQ;
        #pragma unroll
        for (int u = 0; u < NU; u++) {
            int j = lid + u*32;
            float v = ov[u];
            bool inc = (v < lastv) || (v == lastv && j > lasti);
            if (inc && (v > lv || (v == lv && j < li))) { lv = v; li = j; }
        }
        #pragma unroll
        for (int off = 16; off > 0; off >>= 1) {
            float vv = __shfl_xor_sync(0xffffffffu, lv, off);
            int   ii = __shfl_xor_sync(0xffffffffu, li, off);
            if (vv > lv || (vv == lv && ii < li)) { lv = vv; li = ii; }
        }
        kv[t] = lv; ki[t] = li;
        lastv = lv; lasti = li;
    }
    if (lid == 0) {
        float mkv[KK];
        int cnt = 0;
        #pragma unroll
        for (int t = 0; t < KK; t++) {
            float nmk = Mrow[ki[t]];
            float mk  = (kv[t] >= 0.4f) ? nmk : 0.0f;
            mkv[t] = mk;
            if (mk != 0.0f) cnt++;
        }
        int base = (cnt > 0) ? atomicAdd(&g_count, cnt) : 0;
        g_rowbase[r] = base; g_rowcnt[r] = cnt;

        const float* cb = bboxes + (size_t)r * 4;
        float ccx = 0.5f*(cb[0]+cb[2]), ccy = 0.5f*(cb[1]+cb[3]);
        float cw = cb[2]-cb[0], ch = cb[3]-cb[1];
        int s = 0;
        #pragma unroll
        for (int t = 0; t < KK; t++) {
            if (mkv[t] == 0.0f) continue;
            const float* nb = bboxes + (size_t)(b*NQ + ki[t]) * 4;
            float dcx = 0.5f*(nb[0]+nb[2]) - ccx;
            float dcy = 0.5f*(nb[1]+nb[3]) - ccy;
            float dw  = (nb[2]-nb[0]) - cw;
            float dh  = (nb[3]-nb[1]) - ch;
            float4 pm;
            pm.x = logf(fmaxf(fabsf(dcx), 1e-7f));
            pm.y = logf(fmaxf(fabsf(dcy), 1e-7f));
            pm.z = logf(fmaxf(fabsf(dw ), 1e-7f));
            pm.w = logf(fmaxf(fabsf(dh ), 1e-7f));
            g_pm[base+s]    = pm;
            g_w[base+s]     = neg_i * Mrow[ki[t]] * mkv[t];
            g_oval[base+s]  = kv[t] * mkv[t];
            g_mkval[base+s] = mkv[t];
            s++;
        }
    }
}

// ---------------- fp16 mma GEMM: 128x256 tile, BK=32, cp.async dbl-buffer ---
enum { MG1 = 0, MG2 = 1, MC1 = 2, MC2 = 3, MOUT = 4 };
#define BM 128
#define BN 256
#define BK 32
#define PADH 40   /* padded row stride in fp16; 80B -> conflict-free ldmatrix */

#define SA_OFF   0
#define SA_BYTES (BM*PADH*2)            /* 10240 per buf */
#define SB_OFF   (2*SA_BYTES)           /* 20480 */
#define SB_BYTES (BN*PADH*2)            /* 20480 per buf */
#define SBIAS    (SB_OFF + 2*SB_BYTES)  /* 61440 */
#define SS64     (SBIAS + 1024)
#define SPM      (SS64 + 1024)
#define SW       (SPM + 2048)
#define SCOEF    (SW + 512)
#define SMEMSZ   (SCOEF + 256)          /* 66560 */

template<int MODE>
__global__ __launch_bounds__(256, 1)
void gemm_mma(const float* __restrict__ Afe,   // external fp32 A (MC1: tgt)
              const float* __restrict__ bias,
              const float* __restrict__ gmask,
              float* __restrict__ Cfe,         // external fp32 C (MOUT: out)
              int Mext) {
    constexpr bool AASY = (MODE == MG2 || MODE == MC2 || MODE == MOUT); // A via cp.async
    constexpr bool OH   = (MODE == MG1 || MODE == MC1 || MODE == MC2);  // C is fp16

    extern __shared__ __align__(16) char smem[];
    __half* Asm   = (__half*)(smem + SA_OFF);
    __half* Bsm   = (__half*)(smem + SB_OFF);
    float* bias_s = (float*)(smem + SBIAS);
    float* s64_s  = (float*)(smem + SS64);
    float4* pm_s  = (float4*)(smem + SPM);
    float* w_s    = (float*)(smem + SW);
    float* coef_s = (float*)(smem + SCOEF);

    const int Kd = (MODE == MG1) ? WDIM : DD;
    int M = (MODE == MG1 || MODE == MG2) ? g_count : Mext;
    int m0 = blockIdx.x * BM;
    if (m0 >= M) return;

    const __half* Ahp = nullptr;
    const float*  Afp = nullptr;
    const __half* BT;
    __half* Chp = nullptr;
    float*  Cfp = nullptr;
    if (MODE == MG1)      { BT = g_W3T; Chp = g_H; }
    else if (MODE == MG2) { Ahp = g_H;  BT = g_W4T; Cfp = g_feat; }
    else if (MODE == MC1) { Afp = Afe;  BT = g_W1T; Chp = g_T1; }
    else if (MODE == MC2) { Ahp = g_T1; BT = g_W2T; Chp = g_Z; }
    else                  { Ahp = g_Z;  BT = g_W5T; Cfp = Cfe; }

    int tid = threadIdx.x, wid = tid >> 5, lid = tid & 31;
    int gid = lid >> 2, ti = lid & 3;
    int warpM = wid & 1, warpN = wid >> 1;   // 2 x 4 warps, warp tile 64x64

    bias_s[tid] = bias[tid];
    if (MODE == MG1) {
        s64_s[tid] = g_s64[tid];
        if (tid < BM) {
            int rr = m0 + tid;
            if (rr < M) { pm_s[tid] = g_pm[rr]; w_s[tid] = g_w[rr]; }
            else { pm_s[tid] = make_float4(0.f,0.f,0.f,0.f); w_s[tid] = 0.f; }
        }
        if (tid >= 128 && tid < 192)
            coef_s[tid-128] = 6.2831853071795865f *
                              exp2f(-(float)(tid-128) * (13.287712379549450f/64.f));
    }

    uint32_t Asm_b = smem_u32(Asm);
    uint32_t Bsm_b = smem_u32(Bsm);

    // ---- async issue helpers ----
    auto issueB = [&](int c, int buf) {
        #pragma unroll
        for (int i = 0; i < 4; i++) {
            int f = tid + i*256;           // 0..1023
            int row = f >> 2, q = f & 3;
            uint32_t dst = Bsm_b + buf*SB_BYTES + (uint32_t)(row*PADH*2 + q*16);
            const __half* src = BT + (size_t)row*Kd + c*BK + q*8;
            CP16(dst, src);
        }
    };
    auto issueA = [&](int c, int buf) {     // AASY only
        #pragma unroll
        for (int i = 0; i < 2; i++) {
            int f = tid + i*256;           // 0..511
            int row = f >> 2, q = f & 3;
            uint32_t dst = Asm_b + buf*SA_BYTES + (uint32_t)(row*PADH*2 + q*16);
            const __half* src = Ahp + (size_t)(m0 + row)*Kd + c*BK + q*8;
            CP16(dst, src);
        }
    };

    // ---- register staging for generated/converted A ----
    int s_row = tid >> 1;
    int s_kh  = (tid & 1) * 16;
    uint32_t pa[8];
    auto genA = [&](int c) {
        if (MODE == MG1) {
            float4 pm = pm_s[s_row]; float wv = w_s[s_row];
            const float* pmp = (const float*)&pm;
            #pragma unroll
            for (int p = 0; p < 8; p++) {
                int j = c*BK + s_kh + 2*p;               // even j; j and j+1 identical
                int a = j >> 8, sf = (j >> 7) & 1;
                float ang = coef_s[(j & 127) >> 1] * pmp[2*a + sf];
                float v = (sf ? __cosf(ang) : __sinf(ang)) * wv;
                pa[p] = packh2(v, v);
            }
        } else {  // MC1: fp32 -> fp16
            int gr = m0 + s_row;
            const float* ap = Afp + (size_t)gr*Kd + c*BK + s_kh;
            #pragma unroll
            for (int q = 0; q < 4; q++) {
                float4 fv = make_float4(0.f,0.f,0.f,0.f);
                if (gr < M) fv = *(const float4*)(ap + q*4);
                pa[q*2+0] = packh2(fv.x, fv.y);
                pa[q*2+1] = packh2(fv.z, fv.w);
            }
        }
    };
    auto storeA = [&](int buf) {
        uint32_t* ad = (uint32_t*)(smem + SA_OFF + buf*SA_BYTES) + s_row*PADH/ (4/2)  ;
        (void)ad;
        uint32_t* d = (uint32_t*)((char*)smem + SA_OFF + buf*SA_BYTES + s_row*PADH*2 + s_kh*2);
        *(uint4*)(d)     = make_uint4(pa[0], pa[1], pa[2], pa[3]);
        *(uint4*)(d + 4) = make_uint4(pa[4], pa[5], pa[6], pa[7]);
    };

    // ldmatrix per-lane addresses: row = lid&15, k-octet = (lid>>4)*8 fp16
    int l16 = lid & 15, lk = (lid >> 4) * 8;
    uint32_t aaddr = Asm_b + (uint32_t)((warpM*64 + l16) * PADH + lk) * 2u;
    uint32_t baddr = Bsm_b + (uint32_t)((warpN*64 + l16) * PADH + lk) * 2u;

    float acc[4][8][4];
    #pragma unroll
    for (int m = 0; m < 4; m++)
        #pragma unroll
        for (int n = 0; n < 8; n++)
            #pragma unroll
            for (int q = 0; q < 4; q++) acc[m][n][q] = 0.f;

    __syncthreads();   // pm_s/coef_s/bias_s ready

    // ---- prologue: chunk 0 ----
    issueB(0, 0);
    if (AASY) issueA(0, 0);
    CP_COMMIT();
    if (!AASY) { genA(0); storeA(0); }
    CP_WAIT0();
    __syncthreads();

    const int nc = Kd / BK;
    for (int c = 0; c < nc; c++) {
        int buf = c & 1;
        bool pf = (c + 1 < nc);
        if (pf) {
            issueB(c+1, buf ^ 1);
            if (AASY) issueA(c+1, buf ^ 1);
            CP_COMMIT();
            if (!AASY) genA(c+1);
        }
        uint32_t ab = aaddr + buf * SA_BYTES;
        uint32_t bb = baddr + buf * SB_BYTES;
        #pragma unroll
        for (int kb = 0; kb < BK; kb += 16) {
            uint32_t af[4][4], bq[4][4];
            #pragma unroll
            for (int m = 0; m < 4; m++)
                ldsm4(af[m], ab + (uint32_t)((m*16*PADH + kb) * 2));
            #pragma unroll
            for (int g = 0; g < 4; g++)
                ldsm4(bq[g], bb + (uint32_t)((g*16*PADH + kb) * 2));
            #pragma unroll
            for (int m = 0; m < 4; m++) {
                #pragma unroll
                for (int n = 0; n < 8; n++) {
                    uint32_t bfr[2] = { bq[n>>1][n&1], bq[n>>1][(n&1)+2] };
                    mma_f16(acc[m][n], af[m], bfr);
                }
            }
        }
        if (pf) {
            if (!AASY) storeA(buf ^ 1);
            CP_WAIT0();
        }
        __syncthreads();
    }

    // ---- epilogue ----
    #pragma unroll
    for (int m = 0; m < 4; m++) {
        int r0 = m0 + warpM*64 + m*16 + gid;
        int r1 = r0 + 8;
        bool ok0 = r0 < M, ok1 = r1 < M;
        float ovl0 = 0.f, ovl1 = 0.f, ng0 = 1.f, ng1 = 1.f;
        if (MODE == MG1) {
            if (ok0) ovl0 = g_oval[r0];
            if (ok1) ovl1 = g_oval[r1];
        }
        if (MODE == MC2 || MODE == MOUT) {
            if (ok0) ng0 = 1.f - gmask[r0];
            if (ok1) ng1 = 1.f - gmask[r1];
        }
        #pragma unroll
        for (int n = 0; n < 8; n++) {
            int lc = warpN*64 + n*8 + ti*2;
            float b0 = bias_s[lc], b1 = bias_s[lc+1];
            #pragma unroll
            for (int h = 0; h < 2; h++) {
                int row = h ? r1 : r0;
                bool ok = h ? ok1 : ok0;
                if (!ok) continue;
                float ovl = h ? ovl1 : ovl0;
                float ng  = h ? ng1  : ng0;
                float v0 = acc[m][n][h*2+0] + b0;
                float v1 = acc[m][n][h*2+1] + b1;
                if (MODE == MG1) {
                    v0 = fmaxf(v0 + ovl * s64_s[lc],   0.f);
                    v1 = fmaxf(v1 + ovl * s64_s[lc+1], 0.f);
                } else if (MODE == MC1) {
                    v0 = fmaxf(v0, 0.f); v1 = fmaxf(v1, 0.f);
                } else if (MODE == MC2) {
                    const float* ar = g_agg + (size_t)row*DD + lc;
                    v0 = v0 * ng + ar[0];
                    v1 = v1 * ng + ar[1];
                } else if (MODE == MOUT) {
                    v0 = fmaxf(v0, 0.f) * ng; v1 = fmaxf(v1, 0.f) * ng;
                }
                if (OH) {
                    __half2 o = __floats2half2_rn(v0, v1);
                    *(__half2*)(Chp + (size_t)row*DD + lc) = o;
                } else {
                    *(float2*)(Cfp + (size_t)row*DD + lc) = make_float2(v0, v1);
                }
            }
        }
    }
}

// ---------------- masked max over K neighbors -------------------------------
__global__ void k_reduce() {
    int r = blockIdx.x, d = threadIdx.x;
    int base = g_rowbase[r], cnt = g_rowcnt[r];
    float m = (cnt < KK) ? 0.0f : -3.4e38f;
    for (int e = 0; e < cnt; e++)
        m = fmaxf(m, g_mkval[base+e] * g_feat[(size_t)(base+e)*DD + d]);
    g_agg[(size_t)r*DD + d] = m;
}

// ---------------- launch ----------------------------------------------------
extern "C" void kernel_launch(void* const* d_in, const int* in_sizes, int n_in,
                              void* d_out, int out_size) {
    const float* tgt    = (const float*)d_in[0];
    const float* ious   = (const float*)d_in[1];
    const float* bboxes = (const float*)d_in[2];
    const float* gmask  = (const float*)d_in[3];
    const float* W1 = (const float*)d_in[4];  const float* b1 = (const float*)d_in[5];
    const float* W2 = (const float*)d_in[6];  const float* b2 = (const float*)d_in[7];
    const float* W3 = (const float*)d_in[8];  const float* b3 = (const float*)d_in[9];
    const float* W4 = (const float*)d_in[10]; const float* b4 = (const float*)d_in[11];
    const float* W5 = (const float*)d_in[12]; const float* b5 = (const float*)d_in[13];
    float* out = (float*)d_out;

    cudaFuncSetAttribute(gemm_mma<MG1>,  cudaFuncAttributeMaxDynamicSharedMemorySize, SMEMSZ);
    cudaFuncSetAttribute(gemm_mma<MG2>,  cudaFuncAttributeMaxDynamicSharedMemorySize, SMEMSZ);
    cudaFuncSetAttribute(gemm_mma<MC1>,  cudaFuncAttributeMaxDynamicSharedMemorySize, SMEMSZ);
    cudaFuncSetAttribute(gemm_mma<MC2>,  cudaFuncAttributeMaxDynamicSharedMemorySize, SMEMSZ);
    cudaFuncSetAttribute(gemm_mma<MOUT>, cudaFuncAttributeMaxDynamicSharedMemorySize, SMEMSZ);

    k_prep<<<1536, 256>>>(W1, W2, W3, W4, W5);
    k_init<<<1, 256>>>(W3);
    k_topk<<<(ROWS + 7) / 8, 256>>>(ious, gmask, bboxes);

    int gdyn = (FMAX + 127) / 128;   // 563
    int gfix = (ROWS + 127) / 128;   // 57

    gemm_mma<MG1><<<gdyn, 256, SMEMSZ>>>(nullptr, b3, nullptr, nullptr, 0);
    gemm_mma<MG2><<<gdyn, 256, SMEMSZ>>>(nullptr, b4, nullptr, nullptr, 0);
    k_reduce<<<ROWS, DD>>>();
    gemm_mma<MC1><<<gfix, 256, SMEMSZ>>>(tgt,     b1, nullptr, nullptr, ROWS);
    gemm_mma<MC2><<<gfix, 256, SMEMSZ>>>(nullptr, b2, gmask,  nullptr, ROWS);
    gemm_mma<MOUT><<<gfix, 256, SMEMSZ>>>(nullptr, b5, gmask, out,     ROWS);
}

// round 10
// speedup vs baseline: 1.3105x; 1.2547x over previous
#include <cuda_runtime.h>
#include <cuda_fp16.h>
#include <math.h>
#include <stdint.h>

#define BSZ 8
#define NQ 900
#define DD 256
#define KK 10
#define ROWS (BSZ*NQ)        /* 7200  */
#define FMAX (ROWS*KK)       /* 72000 */
#define WDIM 512

// ---------------- scratch (static __device__ arrays; no allocation) ----------
__device__ __align__(256) float4 g_pm[FMAX];
__device__ __align__(256) float  g_w[FMAX];
__device__ __align__(256) float  g_oval[FMAX];
__device__ __align__(256) float  g_mkval[FMAX];
__device__ __align__(256) float  g_feat[(size_t)FMAX*DD];   // fused MG output, fp32
__device__ int    g_rowbase[ROWS];
__device__ int    g_rowcnt[ROWS];
__device__ __align__(256) float  g_agg[(size_t)ROWS*DD];
__device__ float  g_s64[DD];
__device__ int    g_count;
// transposed weights, [N][K] K-major rows, fp16
__device__ __align__(256) __half g_W3T[DD*WDIM];
__device__ __align__(256) __half g_W1T[DD*DD];
__device__ __align__(256) __half g_W2T[DD*DD];
__device__ __align__(256) __half g_W4T[DD*DD];
__device__ __align__(256) __half g_W5T[DD*DD];

__device__ __forceinline__ void mma_f16(float* c, const uint32_t* a, const uint32_t* b) {
    asm volatile(
        "mma.sync.aligned.m16n8k16.row.col.f32.f16.f16.f32 "
        "{%0,%1,%2,%3}, {%4,%5,%6,%7}, {%8,%9}, {%0,%1,%2,%3};"
        : "+f"(c[0]), "+f"(c[1]), "+f"(c[2]), "+f"(c[3])
        : "r"(a[0]), "r"(a[1]), "r"(a[2]), "r"(a[3]), "r"(b[0]), "r"(b[1]));
}
__device__ __forceinline__ void ldsm4(uint32_t* r, uint32_t addr) {
    asm volatile("ldmatrix.sync.aligned.m8n8.x4.shared.b16 {%0,%1,%2,%3}, [%4];"
        : "=r"(r[0]), "=r"(r[1]), "=r"(r[2]), "=r"(r[3]) : "r"(addr));
}
__device__ __forceinline__ uint32_t smem_u32(const void* p) {
    uint32_t a;
    asm("{ .reg .u64 t; cvta.to.shared.u64 t, %1; cvt.u32.u64 %0, t; }" : "=r"(a) : "l"(p));
    return a;
}
__device__ __forceinline__ uint32_t packh2(float a, float b) {
    __half2 h = __floats2half2_rn(a, b);
    return *(uint32_t*)&h;
}
#define CP16(dst, src) asm volatile("cp.async.cg.shared.global [%0], [%1], 16;" :: "r"(dst), "l"(src))
#define CP_COMMIT()    asm volatile("cp.async.commit_group;" ::: "memory")
#define CP_WAIT0()     asm volatile("cp.async.wait_group 0;" ::: "memory")

// ---------------- smem layout (shared by k_mg / k_q) ------------------------
#define PADH 40        /* staged tile row stride, fp16 */
#define HSTR 264       /* H-tile row stride, fp16 (odd 16B-units -> conflict-free) */
#define SA_OFF   0
#define SA_BYTES (128*PADH*2)            /* 10240 */
#define SB_OFF   (2*SA_BYTES)            /* 20480 */
#define SB_BYTES (256*PADH*2)            /* 20480 */
#define SH_OFF   (SB_OFF + 2*SB_BYTES)   /* 61440 */
#define SH_BYTES (128*HSTR*2)            /* 67584 */
#define SC0      (SH_OFF + SH_BYTES)     /* 129024: bias A (1KB) */
#define SC1      (SC0 + 1024)            /* s64 / bias2 */
#define SC2      (SC1 + 1024)            /* bias4 / bias5 */
#define SPM      (SC2 + 1024)            /* 2KB */
#define SW       (SPM + 2048)            /* 512 */
#define SCOEF    (SW + 512)              /* 256 */
#define SMEMSZ   (SCOEF + 256)           /* 134912 */

// ---------------- prep: transpose weights (to fp16) + s64 + counter ---------
__global__ void k_prep(const float* __restrict__ W1, const float* __restrict__ W2,
                       const float* __restrict__ W3, const float* __restrict__ W4,
                       const float* __restrict__ W5) {
    int idx = blockIdx.x * 256 + threadIdx.x;
    if (idx < 131072) {                       // W3T [256][512] from W3[64+k][n]
        int n = idx >> 9, k = idx & 511;
        g_W3T[idx] = __float2half(W3[(size_t)(64 + k) * DD + n]);
    } else {
        int r = idx - 131072;
        int m = r >> 16, e = r & 65535;
        int n = e >> 8, k = e & 255;
        if      (m == 0) g_W1T[e] = __float2half(W1[(size_t)k*DD + n]);
        else if (m == 1) g_W2T[e] = __float2half(W2[(size_t)k*DD + n]);
        else if (m == 2) g_W4T[e] = __float2half(W4[(size_t)k*DD + n]);
        else             g_W5T[e] = __float2half(W5[(size_t)k*DD + n]);
    }
}
__global__ void k_init(const float* __restrict__ W3) {
    int n = threadIdx.x;
    float s = 0.f;
    #pragma unroll 8
    for (int r = 0; r < 64; r++) s += W3[r*DD + n];
    g_s64[n] = s;
    if (n == 0) g_count = 0;
}

// ---------------- top-K: one warp per row, register-resident ----------------
#define NU 29
__global__ __launch_bounds__(256)
void k_topk(const float* __restrict__ ious,
            const float* __restrict__ gmask,
            const float* __restrict__ bboxes) {
    int wid = threadIdx.x >> 5, lid = threadIdx.x & 31;
    int r = blockIdx.x * 8 + wid;
    if (r >= ROWS) return;
    int b = r / NQ, i = r % NQ;
    const float* Mrow = gmask + b*NQ;
    float neg_i = 1.0f - Mrow[i];
    if (neg_i == 0.0f) {
        if (lid == 0) { g_rowbase[r] = 0; g_rowcnt[r] = 0; }
        return;
    }
    const float* irow = ious + (size_t)r * NQ;
    float ov[NU];
    #pragma unroll
    for (int u = 0; u < NU; u++) {
        int j = lid + u*32;
        ov[u] = (j < NQ) ? irow[j] * Mrow[j] * neg_i : -3.4e38f;
    }
    float kv[KK]; int ki[KK];
    float lastv = 3.5e38f; int lasti = -1;
    #pragma unroll
    for (int t = 0; t < KK; t++) {
        float lv = -3.4e38f; int li = NQ;
        #pragma unroll
        for (int u = 0; u < NU; u++) {
            int j = lid + u*32;
            float v = ov[u];
            bool inc = (v < lastv) || (v == lastv && j > lasti);
            if (inc && (v > lv || (v == lv && j < li))) { lv = v; li = j; }
        }
        #pragma unroll
        for (int off = 16; off > 0; off >>= 1) {
            float vv = __shfl_xor_sync(0xffffffffu, lv, off);
            int   ii = __shfl_xor_sync(0xffffffffu, li, off);
            if (vv > lv || (vv == lv && ii < li)) { lv = vv; li = ii; }
        }
        kv[t] = lv; ki[t] = li;
        lastv = lv; lasti = li;
    }
    if (lid == 0) {
        float mkv[KK];
        int cnt = 0;
        #pragma unroll
        for (int t = 0; t < KK; t++) {
            float nmk = Mrow[ki[t]];
            float mk  = (kv[t] >= 0.4f) ? nmk : 0.0f;
            mkv[t] = mk;
            if (mk != 0.0f) cnt++;
        }
        int base = (cnt > 0) ? atomicAdd(&g_count, cnt) : 0;
        g_rowbase[r] = base; g_rowcnt[r] = cnt;

        const float* cb = bboxes + (size_t)r * 4;
        float ccx = 0.5f*(cb[0]+cb[2]), ccy = 0.5f*(cb[1]+cb[3]);
        float cw = cb[2]-cb[0], ch = cb[3]-cb[1];
        int s = 0;
        #pragma unroll
        for (int t = 0; t < KK; t++) {
            if (mkv[t] == 0.0f) continue;
            const float* nb = bboxes + (size_t)(b*NQ + ki[t]) * 4;
            float dcx = 0.5f*(nb[0]+nb[2]) - ccx;
            float dcy = 0.5f*(nb[1]+nb[3]) - ccy;
            float dw  = (nb[2]-nb[0]) - cw;
            float dh  = (nb[3]-nb[1]) - ch;
            float4 pm;
            pm.x = logf(fmaxf(fabsf(dcx), 1e-7f));
            pm.y = logf(fmaxf(fabsf(dcy), 1e-7f));
            pm.z = logf(fmaxf(fabsf(dw ), 1e-7f));
            pm.w = logf(fmaxf(fabsf(dh ), 1e-7f));
            g_pm[base+s]    = pm;
            g_w[base+s]     = neg_i * Mrow[ki[t]] * mkv[t];
            g_oval[base+s]  = kv[t] * mkv[t];
            g_mkval[base+s] = mkv[t];
            s++;
        }
    }
}

// ---------------- GEMM phase helpers (512 thr, tile 128x256, warp 64x32) ----
__device__ __forceinline__ void zero_acc(float acc[4][4][4]) {
    #pragma unroll
    for (int m = 0; m < 4; m++)
        #pragma unroll
        for (int n = 0; n < 4; n++)
            #pragma unroll
            for (int q = 0; q < 4; q++) acc[m][n][q] = 0.f;
}

// MMA on one buffered chunk: A at aab (lane-resolved), B at bbb (lane-resolved)
__device__ __forceinline__ void mma_chunk(uint32_t aab, uint32_t bbb, int astr,
                                          float acc[4][4][4]) {
    #pragma unroll
    for (int kb = 0; kb < 32; kb += 16) {
        uint32_t af[4][4], bq[2][4];
        #pragma unroll
        for (int m = 0; m < 4; m++)
            ldsm4(af[m], aab + (uint32_t)((m*16*astr + kb) * 2));
        #pragma unroll
        for (int g = 0; g < 2; g++)
            ldsm4(bq[g], bbb + (uint32_t)((g*16*PADH + kb) * 2));
        #pragma unroll
        for (int m = 0; m < 4; m++) {
            #pragma unroll
            for (int n = 0; n < 4; n++) {
                uint32_t bfr[2] = { bq[n>>1][n&1], bq[n>>1][(n&1)+2] };
                mma_f16(acc[m][n], af[m], bfr);
            }
        }
    }
}

// phase with staged A (fill functor) ; KD = K depth, B = WT
template<int KD, class F>
__device__ __forceinline__ void phase_staged(
    const __half* __restrict__ WT, char* smem,
    uint32_t aaddr, uint32_t baddr, uint32_t Bsm_b,
    int tid, F fill, float acc[4][4][4]) {
    zero_acc(acc);
    const int s_row = tid >> 2, s_q = tid & 3;
    auto issueB = [&](int c, int buf) {
        #pragma unroll
        for (int i = 0; i < 2; i++) {
            int f = tid + i*512;
            int row = f >> 2, q = f & 3;
            uint32_t dst = Bsm_b + buf*SB_BYTES + (uint32_t)(row*PADH*2 + q*16);
            CP16(dst, WT + (size_t)row*KD + c*32 + q*8);
        }
    };
    auto storeA = [&](int buf, uint4 v) {
        *(uint4*)(smem + SA_OFF + buf*SA_BYTES + (s_row*PADH + s_q*8)*2) = v;
    };
    issueB(0, 0); CP_COMMIT();
    storeA(0, fill(0));
    CP_WAIT0(); __syncthreads();
    const int nc = KD / 32;
    for (int c = 0; c < nc; c++) {
        int buf = c & 1;
        bool pf = (c + 1 < nc);
        uint4 nv;
        if (pf) { issueB(c+1, buf^1); CP_COMMIT(); nv = fill(c+1); }
        mma_chunk(aaddr + buf*SA_BYTES, baddr + buf*SB_BYTES, PADH, acc);
        if (pf) { storeA(buf^1, nv); CP_WAIT0(); }
        __syncthreads();
    }
}

// phase with A resident in H-tile smem (KD=256), B = WT
__device__ __forceinline__ void phase_smemA(
    const __half* __restrict__ WT,
    uint32_t haddr, uint32_t baddr, uint32_t Bsm_b,
    int tid, float acc[4][4][4]) {
    zero_acc(acc);
    auto issueB = [&](int c, int buf) {
        #pragma unroll
        for (int i = 0; i < 2; i++) {
            int f = tid + i*512;
            int row = f >> 2, q = f & 3;
            uint32_t dst = Bsm_b + buf*SB_BYTES + (uint32_t)(row*PADH*2 + q*16);
            CP16(dst, WT + (size_t)row*DD + c*32 + q*8);
        }
    };
    issueB(0, 0); CP_COMMIT();
    CP_WAIT0(); __syncthreads();   // also orders prior Hsm writes vs ldsm reads
    for (int c = 0; c < 8; c++) {
        int buf = c & 1;
        bool pf = (c + 1 < 8);
        if (pf) { issueB(c+1, buf^1); CP_COMMIT(); }
        mma_chunk(haddr + (uint32_t)(c*32*2), baddr + buf*SB_BYTES, HSTR, acc);
        if (pf) { CP_WAIT0(); }
        __syncthreads();
    }
}

// ---------------- fused MG: H = relu(wave@W3+b3+ovl*s64); feat = H@W4+b4 ----
__global__ __launch_bounds__(512, 1)
void k_mg(const float* __restrict__ b3, const float* __restrict__ b4) {
    extern __shared__ __align__(16) char smem[];
    float*  bias3_s = (float*)(smem + SC0);
    float*  s64_s   = (float*)(smem + SC1);
    float*  bias4_s = (float*)(smem + SC2);
    float4* pm_s    = (float4*)(smem + SPM);
    float*  w_s     = (float*)(smem + SW);
    float*  coef_s  = (float*)(smem + SCOEF);

    int M = g_count;
    int m0 = blockIdx.x * 128;
    if (m0 >= M) return;

    int tid = threadIdx.x, wid = tid >> 5, lid = tid & 31;
    int gid = lid >> 2, ti = lid & 3;
    int warpM = wid & 1, warpN = wid >> 1;   // 2 x 8 warps, warp tile 64x32
    int l16 = lid & 15, lk = (lid >> 4) * 8;

    if (tid < 256) { bias3_s[tid] = b3[tid]; s64_s[tid] = g_s64[tid]; bias4_s[tid] = b4[tid]; }
    else if (tid < 384) {
        int rr = m0 + tid - 256;
        if (rr < M) { pm_s[tid-256] = g_pm[rr]; w_s[tid-256] = g_w[rr]; }
        else { pm_s[tid-256] = make_float4(0.f,0.f,0.f,0.f); w_s[tid-256] = 0.f; }
    } else if (tid < 448) {
        coef_s[tid-384] = 6.2831853071795865f *
                          exp2f(-(float)(tid-384) * (13.287712379549450f/64.f));
    }
    __syncthreads();

    uint32_t Asm_b = smem_u32(smem + SA_OFF);
    uint32_t Bsm_b = smem_u32(smem + SB_OFF);
    uint32_t Hsm_b = smem_u32(smem + SH_OFF);
    uint32_t aaddr = Asm_b + (uint32_t)((warpM*64 + l16) * PADH + lk) * 2u;
    uint32_t baddr = Bsm_b + (uint32_t)((warpN*32 + l16) * PADH + lk) * 2u;
    uint32_t haddr = Hsm_b + (uint32_t)((warpM*64 + l16) * HSTR + lk) * 2u;

    float acc[4][4][4];

    // ---- phase 1: wave @ W3T (K=512), A generated on the fly ----
    {
        const int s_row = tid >> 2, s_q = tid & 3;
        float4 pm = pm_s[s_row]; float wv = w_s[s_row];
        auto fill = [&](int c) -> uint4 {
            const float* pmp = (const float*)&pm;
            uint32_t h[4];
            #pragma unroll
            for (int p = 0; p < 4; p++) {
                int j = c*32 + s_q*8 + 2*p;            // even j; pair identical
                int a = j >> 8, sf = (j >> 7) & 1;
                float ang = coef_s[(j & 127) >> 1] * pmp[2*a + sf];
                float v = (sf ? __cosf(ang) : __sinf(ang)) * wv;
                h[p] = packh2(v, v);
            }
            return make_uint4(h[0], h[1], h[2], h[3]);
        };
        phase_staged<WDIM>(g_W3T, smem, aaddr, baddr, Bsm_b, tid, fill, acc);
    }

    // ---- epilogue 1: H into Hsm (fp16) ----
    __half* Hsm = (__half*)(smem + SH_OFF);
    #pragma unroll
    for (int m = 0; m < 4; m++) {
        int rl0 = warpM*64 + m*16 + gid;
        #pragma unroll
        for (int h = 0; h < 2; h++) {
            int rl = rl0 + h*8;
            int rg = m0 + rl;
            float ovl = (rg < M) ? g_oval[rg] : 0.f;
            #pragma unroll
            for (int n = 0; n < 4; n++) {
                int lc = warpN*32 + n*8 + ti*2;
                float v0 = fmaxf(acc[m][n][h*2+0] + bias3_s[lc]   + ovl*s64_s[lc],   0.f);
                float v1 = fmaxf(acc[m][n][h*2+1] + bias3_s[lc+1] + ovl*s64_s[lc+1], 0.f);
                *(__half2*)(Hsm + rl*HSTR + lc) = __floats2half2_rn(v0, v1);
            }
        }
    }
    __syncthreads();

    // ---- phase 2: H @ W4T (K=256) ----
    phase_smemA(g_W4T, haddr, baddr, Bsm_b, tid, acc);

    // ---- epilogue 2: feat (fp32) to global ----
    #pragma unroll
    for (int m = 0; m < 4; m++) {
        int rl0 = warpM*64 + m*16 + gid;
        #pragma unroll
        for (int h = 0; h < 2; h++) {
            int rg = m0 + rl0 + h*8;
            if (rg >= M) continue;
            #pragma unroll
            for (int n = 0; n < 4; n++) {
                int lc = warpN*32 + n*8 + ti*2;
                float v0 = acc[m][n][h*2+0] + bias4_s[lc];
                float v1 = acc[m][n][h*2+1] + bias4_s[lc+1];
                *(float2*)(g_feat + (size_t)rg*DD + lc) = make_float2(v0, v1);
            }
        }
    }
}

// ---------------- masked max over K neighbors -------------------------------
__global__ void k_reduce() {
    int r = blockIdx.x, d = threadIdx.x;
    int base = g_rowbase[r], cnt = g_rowcnt[r];
    float m = (cnt < KK) ? 0.0f : -3.4e38f;
    for (int e = 0; e < cnt; e++)
        m = fmaxf(m, g_mkval[base+e] * g_feat[(size_t)(base+e)*DD + d]);
    g_agg[(size_t)r*DD + d] = m;
}

// ---------------- fused query chain: T1 -> Z -> out -------------------------
__global__ __launch_bounds__(512, 1)
void k_q(const float* __restrict__ tgt, const float* __restrict__ gmask,
         const float* __restrict__ b1, const float* __restrict__ b2,
         const float* __restrict__ b5, float* __restrict__ out) {
    extern __shared__ __align__(16) char smem[];
    float* bias1_s = (float*)(smem + SC0);
    float* bias2_s = (float*)(smem + SC1);
    float* bias5_s = (float*)(smem + SC2);

    const int M = ROWS;
    int m0 = blockIdx.x * 128;

    int tid = threadIdx.x, wid = tid >> 5, lid = tid & 31;
    int gid = lid >> 2, ti = lid & 3;
    int warpM = wid & 1, warpN = wid >> 1;
    int l16 = lid & 15, lk = (lid >> 4) * 8;

    if (tid < 256) { bias1_s[tid] = b1[tid]; bias2_s[tid] = b2[tid]; bias5_s[tid] = b5[tid]; }
    __syncthreads();

    uint32_t Asm_b = smem_u32(smem + SA_OFF);
    uint32_t Bsm_b = smem_u32(smem + SB_OFF);
    uint32_t Hsm_b = smem_u32(smem + SH_OFF);
    uint32_t aaddr = Asm_b + (uint32_t)((warpM*64 + l16) * PADH + lk) * 2u;
    uint32_t baddr = Bsm_b + (uint32_t)((warpN*32 + l16) * PADH + lk) * 2u;
    uint32_t haddr = Hsm_b + (uint32_t)((warpM*64 + l16) * HSTR + lk) * 2u;
    __half* Hsm = (__half*)(smem + SH_OFF);

    float acc[4][4][4];

    // ---- phase 1: relu(tgt @ W1T + b1) -> Hsm ----
    {
        const int s_row = tid >> 2, s_q = tid & 3;
        auto fill = [&](int c) -> uint4 {
            int gr = m0 + s_row;
            float4 f0 = make_float4(0.f,0.f,0.f,0.f), f1 = f0;
            if (gr < M) {
                const float* ap = tgt + (size_t)gr*DD + c*32 + s_q*8;
                f0 = *(const float4*)ap; f1 = *(const float4*)(ap + 4);
            }
            return make_uint4(packh2(f0.x,f0.y), packh2(f0.z,f0.w),
                              packh2(f1.x,f1.y), packh2(f1.z,f1.w));
        };
        phase_staged<DD>(g_W1T, smem, aaddr, baddr, Bsm_b, tid, fill, acc);
    }
    #pragma unroll
    for (int m = 0; m < 4; m++) {
        int rl0 = warpM*64 + m*16 + gid;
        #pragma unroll
        for (int h = 0; h < 2; h++) {
            int rl = rl0 + h*8;
            #pragma unroll
            for (int n = 0; n < 4; n++) {
                int lc = warpN*32 + n*8 + ti*2;
                float v0 = fmaxf(acc[m][n][h*2+0] + bias1_s[lc],   0.f);
                float v1 = fmaxf(acc[m][n][h*2+1] + bias1_s[lc+1], 0.f);
                *(__half2*)(Hsm + rl*HSTR + lc) = __floats2half2_rn(v0, v1);
            }
        }
    }
    __syncthreads();

    // ---- phase 2: Z = (T1 @ W2T + b2)*neg + agg -> Hsm ----
    phase_smemA(g_W2T, haddr, baddr, Bsm_b, tid, acc);
    #pragma unroll
    for (int m = 0; m < 4; m++) {
        int rl0 = warpM*64 + m*16 + gid;
        #pragma unroll
        for (int h = 0; h < 2; h++) {
            int rl = rl0 + h*8;
            int rg = m0 + rl;
            if (rg >= M) continue;
            float ng = 1.f - gmask[rg];
            const float* ar = g_agg + (size_t)rg*DD;
            #pragma unroll
            for (int n = 0; n < 4; n++) {
                int lc = warpN*32 + n*8 + ti*2;
                float v0 = (acc[m][n][h*2+0] + bias2_s[lc])   * ng + ar[lc];
                float v1 = (acc[m][n][h*2+1] + bias2_s[lc+1]) * ng + ar[lc+1];
                *(__half2*)(Hsm + rl*HSTR + lc) = __floats2half2_rn(v0, v1);
            }
        }
    }
    __syncthreads();

    // ---- phase 3: out = relu(Z @ W5T + b5) * neg ----
    phase_smemA(g_W5T, haddr, baddr, Bsm_b, tid, acc);
    #pragma unroll
    for (int m = 0; m < 4; m++) {
        int rl0 = warpM*64 + m*16 + gid;
        #pragma unroll
        for (int h = 0; h < 2; h++) {
            int rg = m0 + rl0 + h*8;
            if (rg >= M) continue;
            float ng = 1.f - gmask[rg];
            #pragma unroll
            for (int n = 0; n < 4; n++) {
                int lc = warpN*32 + n*8 + ti*2;
                float v0 = fmaxf(acc[m][n][h*2+0] + bias5_s[lc],   0.f) * ng;
                float v1 = fmaxf(acc[m][n][h*2+1] + bias5_s[lc+1], 0.f) * ng;
                *(float2*)(out + (size_t)rg*DD + lc) = make_float2(v0, v1);
            }
        }
    }
}

// ---------------- launch ----------------------------------------------------
extern "C" void kernel_launch(void* const* d_in, const int* in_sizes, int n_in,
                              void* d_out, int out_size) {
    const float* tgt    = (const float*)d_in[0];
    const float* ious   = (const float*)d_in[1];
    const float* bboxes = (const float*)d_in[2];
    const float* gmask  = (const float*)d_in[3];
    const float* W1 = (const float*)d_in[4];  const float* b1 = (const float*)d_in[5];
    const float* W2 = (const float*)d_in[6];  const float* b2 = (const float*)d_in[7];
    const float* W3 = (const float*)d_in[8];  const float* b3 = (const float*)d_in[9];
    const float* W4 = (const float*)d_in[10]; const float* b4 = (const float*)d_in[11];
    const float* W5 = (const float*)d_in[12]; const float* b5 = (const float*)d_in[13];
    float* out = (float*)d_out;

    cudaFuncSetAttribute(k_mg, cudaFuncAttributeMaxDynamicSharedMemorySize, SMEMSZ);
    cudaFuncSetAttribute(k_q,  cudaFuncAttributeMaxDynamicSharedMemorySize, SMEMSZ);

    k_prep<<<1536, 256>>>(W1, W2, W3, W4, W5);
    k_init<<<1, 256>>>(W3);
    k_topk<<<(ROWS + 7) / 8, 256>>>(ious, gmask, bboxes);

    k_mg<<<(FMAX + 127) / 128, 512, SMEMSZ>>>(b3, b4);
    k_reduce<<<ROWS, DD>>>();
    k_q<<<(ROWS + 127) / 128, 512, SMEMSZ>>>(tgt, gmask, b1, b2, b5, out);
}

// round 11
// speedup vs baseline: 1.3272x; 1.0128x over previous
#include <cuda_runtime.h>
#include <cuda_fp16.h>
#include <math.h>
#include <stdint.h>

#define BSZ 8
#define NQ 900
#define DD 256
#define KK 10
#define ROWS (BSZ*NQ)        /* 7200  */
#define FMAX (ROWS*KK)       /* 72000 */
#define WDIM 512

// ---------------- scratch (static __device__ arrays; no allocation) ----------
__device__ __align__(256) float4 g_pm[FMAX];
__device__ __align__(256) float  g_w[FMAX];
__device__ __align__(256) float  g_oval[FMAX];
__device__ __align__(256) float  g_mkval[FMAX];
__device__ __align__(256) float  g_feat[(size_t)FMAX*DD];   // fused MG output, fp32
__device__ int    g_rowbase[ROWS];
__device__ int    g_rowcnt[ROWS];
__device__ __align__(256) float  g_agg[(size_t)ROWS*DD];
__device__ float  g_s64[DD];
__device__ int    g_count;
// transposed weights, [N][K] K-major rows, fp16
__device__ __align__(256) __half g_W3T[DD*WDIM];
__device__ __align__(256) __half g_W1T[DD*DD];
__device__ __align__(256) __half g_W2T[DD*DD];
__device__ __align__(256) __half g_W4T[DD*DD];
__device__ __align__(256) __half g_W5T[DD*DD];

__device__ __forceinline__ void mma_f16(float* c, const uint32_t* a, const uint32_t* b) {
    asm volatile(
        "mma.sync.aligned.m16n8k16.row.col.f32.f16.f16.f32 "
        "{%0,%1,%2,%3}, {%4,%5,%6,%7}, {%8,%9}, {%0,%1,%2,%3};"
        : "+f"(c[0]), "+f"(c[1]), "+f"(c[2]), "+f"(c[3])
        : "r"(a[0]), "r"(a[1]), "r"(a[2]), "r"(a[3]), "r"(b[0]), "r"(b[1]));
}
__device__ __forceinline__ void ldsm4(uint32_t* r, uint32_t addr) {
    asm volatile("ldmatrix.sync.aligned.m8n8.x4.shared.b16 {%0,%1,%2,%3}, [%4];"
        : "=r"(r[0]), "=r"(r[1]), "=r"(r[2]), "=r"(r[3]) : "r"(addr));
}
__device__ __forceinline__ uint32_t smem_u32(const void* p) {
    uint32_t a;
    asm("{ .reg .u64 t; cvta.to.shared.u64 t, %1; cvt.u32.u64 %0, t; }" : "=r"(a) : "l"(p));
    return a;
}
__device__ __forceinline__ uint32_t packh2(float a, float b) {
    __half2 h = __floats2half2_rn(a, b);
    return *(uint32_t*)&h;
}
#define CP16(dst, src) asm volatile("cp.async.cg.shared.global [%0], [%1], 16;" :: "r"(dst), "l"(src))
#define CP_COMMIT()    asm volatile("cp.async.commit_group;" ::: "memory")
#define CP_WAIT0()     asm volatile("cp.async.wait_group 0;" ::: "memory")

// ---------------- smem layout (BM=64, 256 threads, 2 CTAs/SM target) --------
#define PADH 40        /* staged tile row stride, fp16 */
#define HSTR 264       /* H-tile row stride, fp16 */
#define SA_OFF   0
#define SA_BYTES (64*PADH*2)             /* 5120 per buf  */
#define SB_OFF   (2*SA_BYTES)            /* 10240 */
#define SB_BYTES (256*PADH*2)            /* 20480 per buf */
#define SH_OFF   (SB_OFF + 2*SB_BYTES)   /* 51200 */
#define SH_BYTES (64*HSTR*2)             /* 33792 */
#define SC0      (SH_OFF + SH_BYTES)     /* 84992 */
#define SC1      (SC0 + 1024)
#define SC2      (SC1 + 1024)
#define SPM      (SC2 + 1024)            /* 64 x float4 = 1KB */
#define SW       (SPM + 1024)            /* 256B */
#define SCOEF    (SW + 256)              /* 256B */
#define SMEMSZ   (SCOEF + 256)           /* 89600 -> 2 CTAs/SM */

// ---------------- prep: transpose weights (to fp16) + s64 + counter ---------
__global__ void k_prep(const float* __restrict__ W1, const float* __restrict__ W2,
                       const float* __restrict__ W3, const float* __restrict__ W4,
                       const float* __restrict__ W5) {
    int idx = blockIdx.x * 256 + threadIdx.x;
    if (idx < 131072) {                       // W3T [256][512] from W3[64+k][n]
        int n = idx >> 9, k = idx & 511;
        g_W3T[idx] = __float2half(W3[(size_t)(64 + k) * DD + n]);
    } else {
        int r = idx - 131072;
        int m = r >> 16, e = r & 65535;
        int n = e >> 8, k = e & 255;
        if      (m == 0) g_W1T[e] = __float2half(W1[(size_t)k*DD + n]);
        else if (m == 1) g_W2T[e] = __float2half(W2[(size_t)k*DD + n]);
        else if (m == 2) g_W4T[e] = __float2half(W4[(size_t)k*DD + n]);
        else             g_W5T[e] = __float2half(W5[(size_t)k*DD + n]);
    }
}
__global__ void k_init(const float* __restrict__ W3) {
    int n = threadIdx.x;
    float s = 0.f;
    #pragma unroll 8
    for (int r = 0; r < 64; r++) s += W3[r*DD + n];
    g_s64[n] = s;
    if (n == 0) g_count = 0;
}

// ---------------- top-K: one warp per row, register-resident ----------------
#define NU 29
__global__ __launch_bounds__(256)
void k_topk(const float* __restrict__ ious,
            const float* __restrict__ gmask,
            const float* __restrict__ bboxes) {
    int wid = threadIdx.x >> 5, lid = threadIdx.x & 31;
    int r = blockIdx.x * 8 + wid;
    if (r >= ROWS) return;
    int b = r / NQ, i = r % NQ;
    const float* Mrow = gmask + b*NQ;
    float neg_i = 1.0f - Mrow[i];
    if (neg_i == 0.0f) {
        if (lid == 0) { g_rowbase[r] = 0; g_rowcnt[r] = 0; }
        return;
    }
    const float* irow = ious + (size_t)r * NQ;
    float ov[NU];
    #pragma unroll
    for (int u = 0; u < NU; u++) {
        int j = lid + u*32;
        ov[u] = (j < NQ) ? irow[j] * Mrow[j] * neg_i : -3.4e38f;
    }
    float kv[KK]; int ki[KK];
    float lastv = 3.5e38f; int lasti = -1;
    #pragma unroll
    for (int t = 0; t < KK; t++) {
        float lv = -3.4e38f; int li = NQ;
        #pragma unroll
        for (int u = 0; u < NU; u++) {
            int j = lid + u*32;
            float v = ov[u];
            bool inc = (v < lastv) || (v == lastv && j > lasti);
            if (inc && (v > lv || (v == lv && j < li))) { lv = v; li = j; }
        }
        #pragma unroll
        for (int off = 16; off > 0; off >>= 1) {
            float vv = __shfl_xor_sync(0xffffffffu, lv, off);
            int   ii = __shfl_xor_sync(0xffffffffu, li, off);
            if (vv > lv || (vv == lv && ii < li)) { lv = vv; li = ii; }
        }
        kv[t] = lv; ki[t] = li;
        lastv = lv; lasti = li;
    }
    if (lid == 0) {
        float mkv[KK];
        int cnt = 0;
        #pragma unroll
        for (int t = 0; t < KK; t++) {
            float nmk = Mrow[ki[t]];
            float mk  = (kv[t] >= 0.4f) ? nmk : 0.0f;
            mkv[t] = mk;
            if (mk != 0.0f) cnt++;
        }
        int base = (cnt > 0) ? atomicAdd(&g_count, cnt) : 0;
        g_rowbase[r] = base; g_rowcnt[r] = cnt;

        const float* cb = bboxes + (size_t)r * 4;
        float ccx = 0.5f*(cb[0]+cb[2]), ccy = 0.5f*(cb[1]+cb[3]);
        float cw = cb[2]-cb[0], ch = cb[3]-cb[1];
        int s = 0;
        #pragma unroll
        for (int t = 0; t < KK; t++) {
            if (mkv[t] == 0.0f) continue;
            const float* nb = bboxes + (size_t)(b*NQ + ki[t]) * 4;
            float dcx = 0.5f*(nb[0]+nb[2]) - ccx;
            float dcy = 0.5f*(nb[1]+nb[3]) - ccy;
            float dw  = (nb[2]-nb[0]) - cw;
            float dh  = (nb[3]-nb[1]) - ch;
            float4 pm;
            pm.x = logf(fmaxf(fabsf(dcx), 1e-7f));
            pm.y = logf(fmaxf(fabsf(dcy), 1e-7f));
            pm.z = logf(fmaxf(fabsf(dw ), 1e-7f));
            pm.w = logf(fmaxf(fabsf(dh ), 1e-7f));
            g_pm[base+s]    = pm;
            g_w[base+s]     = neg_i * Mrow[ki[t]] * mkv[t];
            g_oval[base+s]  = kv[t] * mkv[t];
            g_mkval[base+s] = mkv[t];
            s++;
        }
    }
}

// ---------------- GEMM phase helpers (256 thr, tile 64x256, warp 64x32) -----
__device__ __forceinline__ void zero_acc(float acc[4][4][4]) {
    #pragma unroll
    for (int m = 0; m < 4; m++)
        #pragma unroll
        for (int n = 0; n < 4; n++)
            #pragma unroll
            for (int q = 0; q < 4; q++) acc[m][n][q] = 0.f;
}

// MMA on one buffered chunk (64 rows of A, 32 cols for this warp's N slice)
__device__ __forceinline__ void mma_chunk(uint32_t aab, uint32_t bbb, int astr,
                                          float acc[4][4][4]) {
    #pragma unroll
    for (int kb = 0; kb < 32; kb += 16) {
        uint32_t af[4][4], bq[2][4];
        #pragma unroll
        for (int m = 0; m < 4; m++)
            ldsm4(af[m], aab + (uint32_t)((m*16*astr + kb) * 2));
        #pragma unroll
        for (int g = 0; g < 2; g++)
            ldsm4(bq[g], bbb + (uint32_t)((g*16*PADH + kb) * 2));
        #pragma unroll
        for (int m = 0; m < 4; m++) {
            #pragma unroll
            for (int n = 0; n < 4; n++) {
                uint32_t bfr[2] = { bq[n>>1][n&1], bq[n>>1][(n&1)+2] };
                mma_f16(acc[m][n], af[m], bfr);
            }
        }
    }
}

// phase with staged A (fill functor); KD = K depth, B = WT
template<int KD, class F>
__device__ __forceinline__ void phase_staged(
    const __half* __restrict__ WT, char* smem,
    uint32_t aaddr, uint32_t baddr, uint32_t Bsm_b,
    int tid, F fill, float acc[4][4][4]) {
    zero_acc(acc);
    const int s_row = tid >> 2, s_q = tid & 3;   // 64 rows x 4 quads
    auto issueB = [&](int c, int buf) {
        #pragma unroll
        for (int i = 0; i < 4; i++) {
            int f = tid + i*256;                 // 1024 x 16B = full B chunk
            int row = f >> 2, q = f & 3;
            uint32_t dst = Bsm_b + buf*SB_BYTES + (uint32_t)(row*PADH*2 + q*16);
            CP16(dst, WT + (size_t)row*KD + c*32 + q*8);
        }
    };
    auto storeA = [&](int buf, uint4 v) {
        *(uint4*)(smem + SA_OFF + buf*SA_BYTES + (s_row*PADH + s_q*8)*2) = v;
    };
    issueB(0, 0); CP_COMMIT();
    storeA(0, fill(0));
    CP_WAIT0(); __syncthreads();
    const int nc = KD / 32;
    for (int c = 0; c < nc; c++) {
        int buf = c & 1;
        bool pf = (c + 1 < nc);
        uint4 nv;
        if (pf) { issueB(c+1, buf^1); CP_COMMIT(); nv = fill(c+1); }
        mma_chunk(aaddr + buf*SA_BYTES, baddr + buf*SB_BYTES, PADH, acc);
        if (pf) { storeA(buf^1, nv); CP_WAIT0(); }
        __syncthreads();
    }
}

// phase with A resident in H-tile smem (KD=256), B = WT
__device__ __forceinline__ void phase_smemA(
    const __half* __restrict__ WT,
    uint32_t haddr, uint32_t baddr, uint32_t Bsm_b,
    int tid, float acc[4][4][4]) {
    zero_acc(acc);
    auto issueB = [&](int c, int buf) {
        #pragma unroll
        for (int i = 0; i < 4; i++) {
            int f = tid + i*256;
            int row = f >> 2, q = f & 3;
            uint32_t dst = Bsm_b + buf*SB_BYTES + (uint32_t)(row*PADH*2 + q*16);
            CP16(dst, WT + (size_t)row*DD + c*32 + q*8);
        }
    };
    issueB(0, 0); CP_COMMIT();
    CP_WAIT0(); __syncthreads();   // also orders prior Hsm writes vs ldsm reads
    for (int c = 0; c < 8; c++) {
        int buf = c & 1;
        bool pf = (c + 1 < 8);
        if (pf) { issueB(c+1, buf^1); CP_COMMIT(); }
        mma_chunk(haddr + (uint32_t)(c*32*2), baddr + buf*SB_BYTES, HSTR, acc);
        if (pf) { CP_WAIT0(); }
        __syncthreads();
    }
}

// ---------------- fused MG: H = relu(wave@W3+b3+ovl*s64); feat = H@W4+b4 ----
__global__ __launch_bounds__(256, 2)
void k_mg(const float* __restrict__ b3, const float* __restrict__ b4) {
    extern __shared__ __align__(16) char smem[];
    float*  bias3_s = (float*)(smem + SC0);
    float*  s64_s   = (float*)(smem + SC1);
    float*  bias4_s = (float*)(smem + SC2);
    float4* pm_s    = (float4*)(smem + SPM);
    float*  w_s     = (float*)(smem + SW);
    float*  coef_s  = (float*)(smem + SCOEF);

    int M = g_count;
    int m0 = blockIdx.x * 64;
    if (m0 >= M) return;

    int tid = threadIdx.x, wid = tid >> 5, lid = tid & 31;
    int gid = lid >> 2, ti = lid & 3;
    int warpN = wid;                          // 8 warps, warp tile 64x32
    int l16 = lid & 15, lk = (lid >> 4) * 8;

    bias3_s[tid] = b3[tid & 255]; s64_s[tid] = g_s64[tid & 255]; bias4_s[tid] = b4[tid & 255];
    if (tid < 64) {
        int rr = m0 + tid;
        if (rr < M) { pm_s[tid] = g_pm[rr]; w_s[tid] = g_w[rr]; }
        else { pm_s[tid] = make_float4(0.f,0.f,0.f,0.f); w_s[tid] = 0.f; }
        coef_s[tid] = 6.2831853071795865f *
                      exp2f(-(float)tid * (13.287712379549450f/64.f));
    }
    __syncthreads();

    uint32_t Asm_b = smem_u32(smem + SA_OFF);
    uint32_t Bsm_b = smem_u32(smem + SB_OFF);
    uint32_t Hsm_b = smem_u32(smem + SH_OFF);
    uint32_t aaddr = Asm_b + (uint32_t)(l16 * PADH + lk) * 2u;
    uint32_t baddr = Bsm_b + (uint32_t)((warpN*32 + l16) * PADH + lk) * 2u;
    uint32_t haddr = Hsm_b + (uint32_t)(l16 * HSTR + lk) * 2u;

    float acc[4][4][4];

    // ---- phase 1: wave @ W3T (K=512), A generated on the fly ----
    {
        const int s_row = tid >> 2, s_q = tid & 3;
        float4 pm = pm_s[s_row]; float wv = w_s[s_row];
        auto fill = [&](int c) -> uint4 {
            const float* pmp = (const float*)&pm;
            uint32_t h[4];
            #pragma unroll
            for (int p = 0; p < 4; p++) {
                int j = c*32 + s_q*8 + 2*p;            // even j; pair identical
                int a = j >> 8, sf = (j >> 7) & 1;
                float ang = coef_s[(j & 127) >> 1] * pmp[2*a + sf];
                float v = (sf ? __cosf(ang) : __sinf(ang)) * wv;
                h[p] = packh2(v, v);
            }
            return make_uint4(h[0], h[1], h[2], h[3]);
        };
        phase_staged<WDIM>(g_W3T, smem, aaddr, baddr, Bsm_b, tid, fill, acc);
    }

    // ---- epilogue 1: H into Hsm (fp16) ----
    __half* Hsm = (__half*)(smem + SH_OFF);
    #pragma unroll
    for (int m = 0; m < 4; m++) {
        int rl0 = m*16 + gid;
        #pragma unroll
        for (int h = 0; h < 2; h++) {
            int rl = rl0 + h*8;
            int rg = m0 + rl;
            float ovl = (rg < M) ? g_oval[rg] : 0.f;
            #pragma unroll
            for (int n = 0; n < 4; n++) {
                int lc = warpN*32 + n*8 + ti*2;
                float v0 = fmaxf(acc[m][n][h*2+0] + bias3_s[lc]   + ovl*s64_s[lc],   0.f);
                float v1 = fmaxf(acc[m][n][h*2+1] + bias3_s[lc+1] + ovl*s64_s[lc+1], 0.f);
                *(__half2*)(Hsm + rl*HSTR + lc) = __floats2half2_rn(v0, v1);
            }
        }
    }
    __syncthreads();

    // ---- phase 2: H @ W4T (K=256) ----
    phase_smemA(g_W4T, haddr, baddr, Bsm_b, tid, acc);

    // ---- epilogue 2: feat (fp32) to global ----
    #pragma unroll
    for (int m = 0; m < 4; m++) {
        int rl0 = m*16 + gid;
        #pragma unroll
        for (int h = 0; h < 2; h++) {
            int rg = m0 + rl0 + h*8;
            if (rg >= M) continue;
            #pragma unroll
            for (int n = 0; n < 4; n++) {
                int lc = warpN*32 + n*8 + ti*2;
                float v0 = acc[m][n][h*2+0] + bias4_s[lc];
                float v1 = acc[m][n][h*2+1] + bias4_s[lc+1];
                *(float2*)(g_feat + (size_t)rg*DD + lc) = make_float2(v0, v1);
            }
        }
    }
}

// ---------------- masked max over K neighbors -------------------------------
__global__ void k_reduce() {
    int r = blockIdx.x, d = threadIdx.x;
    int base = g_rowbase[r], cnt = g_rowcnt[r];
    float m = (cnt < KK) ? 0.0f : -3.4e38f;
    for (int e = 0; e < cnt; e++)
        m = fmaxf(m, g_mkval[base+e] * g_feat[(size_t)(base+e)*DD + d]);
    g_agg[(size_t)r*DD + d] = m;
}

// ---------------- fused query chain: T1 -> Z -> out -------------------------
__global__ __launch_bounds__(256, 2)
void k_q(const float* __restrict__ tgt, const float* __restrict__ gmask,
         const float* __restrict__ b1, const float* __restrict__ b2,
         const float* __restrict__ b5, float* __restrict__ out) {
    extern __shared__ __align__(16) char smem[];
    float* bias1_s = (float*)(smem + SC0);
    float* bias2_s = (float*)(smem + SC1);
    float* bias5_s = (float*)(smem + SC2);

    const int M = ROWS;
    int m0 = blockIdx.x * 64;
    if (m0 >= M) return;

    int tid = threadIdx.x, wid = tid >> 5, lid = tid & 31;
    int gid = lid >> 2, ti = lid & 3;
    int warpN = wid;
    int l16 = lid & 15, lk = (lid >> 4) * 8;

    bias1_s[tid] = b1[tid & 255]; bias2_s[tid] = b2[tid & 255]; bias5_s[tid] = b5[tid & 255];
    __syncthreads();

    uint32_t Asm_b = smem_u32(smem + SA_OFF);
    uint32_t Bsm_b = smem_u32(smem + SB_OFF);
    uint32_t Hsm_b = smem_u32(smem + SH_OFF);
    uint32_t aaddr = Asm_b + (uint32_t)(l16 * PADH + lk) * 2u;
    uint32_t baddr = Bsm_b + (uint32_t)((warpN*32 + l16) * PADH + lk) * 2u;
    uint32_t haddr = Hsm_b + (uint32_t)(l16 * HSTR + lk) * 2u;
    __half* Hsm = (__half*)(smem + SH_OFF);

    float acc[4][4][4];

    // ---- phase 1: relu(tgt @ W1T + b1) -> Hsm ----
    {
        const int s_row = tid >> 2, s_q = tid & 3;
        auto fill = [&](int c) -> uint4 {
            int gr = m0 + s_row;
            float4 f0 = make_float4(0.f,0.f,0.f,0.f), f1 = f0;
            if (gr < M) {
                const float* ap = tgt + (size_t)gr*DD + c*32 + s_q*8;
                f0 = *(const float4*)ap; f1 = *(const float4*)(ap + 4);
            }
            return make_uint4(packh2(f0.x,f0.y), packh2(f0.z,f0.w),
                              packh2(f1.x,f1.y), packh2(f1.z,f1.w));
        };
        phase_staged<DD>(g_W1T, smem, aaddr, baddr, Bsm_b, tid, fill, acc);
    }
    #pragma unroll
    for (int m = 0; m < 4; m++) {
        int rl0 = m*16 + gid;
        #pragma unroll
        for (int h = 0; h < 2; h++) {
            int rl = rl0 + h*8;
            #pragma unroll
            for (int n = 0; n < 4; n++) {
                int lc = warpN*32 + n*8 + ti*2;
                float v0 = fmaxf(acc[m][n][h*2+0] + bias1_s[lc],   0.f);
                float v1 = fmaxf(acc[m][n][h*2+1] + bias1_s[lc+1], 0.f);
                *(__half2*)(Hsm + rl*HSTR + lc) = __floats2half2_rn(v0, v1);
            }
        }
    }
    __syncthreads();

    // ---- phase 2: Z = (T1 @ W2T + b2)*neg + agg -> Hsm ----
    phase_smemA(g_W2T, haddr, baddr, Bsm_b, tid, acc);
    #pragma unroll
    for (int m = 0; m < 4; m++) {
        int rl0 = m*16 + gid;
        #pragma unroll
        for (int h = 0; h < 2; h++) {
            int rl = rl0 + h*8;
            int rg = m0 + rl;
            if (rg >= M) continue;
            float ng = 1.f - gmask[rg];
            const float* ar = g_agg + (size_t)rg*DD;
            #pragma unroll
            for (int n = 0; n < 4; n++) {
                int lc = warpN*32 + n*8 + ti*2;
                float v0 = (acc[m][n][h*2+0] + bias2_s[lc])   * ng + ar[lc];
                float v1 = (acc[m][n][h*2+1] + bias2_s[lc+1]) * ng + ar[lc+1];
                *(__half2*)(Hsm + rl*HSTR + lc) = __floats2half2_rn(v0, v1);
            }
        }
    }
    __syncthreads();

    // ---- phase 3: out = relu(Z @ W5T + b5) * neg ----
    phase_smemA(g_W5T, haddr, baddr, Bsm_b, tid, acc);
    #pragma unroll
    for (int m = 0; m < 4; m++) {
        int rl0 = m*16 + gid;
        #pragma unroll
        for (int h = 0; h < 2; h++) {
            int rg = m0 + rl0 + h*8;
            if (rg >= M) continue;
            float ng = 1.f - gmask[rg];
            #pragma unroll
            for (int n = 0; n < 4; n++) {
                int lc = warpN*32 + n*8 + ti*2;
                float v0 = fmaxf(acc[m][n][h*2+0] + bias5_s[lc],   0.f) * ng;
                float v1 = fmaxf(acc[m][n][h*2+1] + bias5_s[lc+1], 0.f) * ng;
                *(float2*)(out + (size_t)rg*DD + lc) = make_float2(v0, v1);
            }
        }
    }
}

// ---------------- launch ----------------------------------------------------
extern "C" void kernel_launch(void* const* d_in, const int* in_sizes, int n_in,
                              void* d_out, int out_size) {
    const float* tgt    = (const float*)d_in[0];
    const float* ious   = (const float*)d_in[1];
    const float* bboxes = (const float*)d_in[2];
    const float* gmask  = (const float*)d_in[3];
    const float* W1 = (const float*)d_in[4];  const float* b1 = (const float*)d_in[5];
    const float* W2 = (const float*)d_in[6];  const float* b2 = (const float*)d_in[7];
    const float* W3 = (const float*)d_in[8];  const float* b3 = (const float*)d_in[9];
    const float* W4 = (const float*)d_in[10]; const float* b4 = (const float*)d_in[11];
    const float* W5 = (const float*)d_in[12]; const float* b5 = (const float*)d_in[13];
    float* out = (float*)d_out;

    cudaFuncSetAttribute(k_mg, cudaFuncAttributeMaxDynamicSharedMemorySize, SMEMSZ);
    cudaFuncSetAttribute(k_q,  cudaFuncAttributeMaxDynamicSharedMemorySize, SMEMSZ);

    k_prep<<<1536, 256>>>(W1, W2, W3, W4, W5);
    k_init<<<1, 256>>>(W3);
    k_topk<<<(ROWS + 7) / 8, 256>>>(ious, gmask, bboxes);

    k_mg<<<(FMAX + 63) / 64, 256, SMEMSZ>>>(b3, b4);
    k_reduce<<<ROWS, DD>>>();
    k_q<<<(ROWS + 63) / 64, 256, SMEMSZ>>>(tgt, gmask, b1, b2, b5, out);
}

// round 12
// speedup vs baseline: 1.5171x; 1.1431x over previous
#include <cuda_runtime.h>
#include <cuda_fp16.h>
#include <math.h>
#include <stdint.h>

#define BSZ 8
#define NQ 900
#define DD 256
#define KK 10
#define ROWS (BSZ*NQ)        /* 7200  */
#define FMAX (ROWS*KK)       /* 72000 */
#define WDIM 512

// ---------------- scratch (static __device__ arrays; no allocation) ----------
__device__ __align__(256) float4 g_pm[FMAX];
__device__ __align__(256) float  g_w[FMAX];
__device__ __align__(256) float  g_oval[FMAX];
__device__ __align__(256) float  g_mkval[FMAX];
__device__ __align__(256) float  g_feat[(size_t)FMAX*DD];   // fused MG output, fp32
__device__ int    g_rowbase[ROWS];
__device__ int    g_rowcnt[ROWS];
__device__ __align__(256) float  g_agg[(size_t)ROWS*DD];
__device__ float  g_s64[DD];
__device__ int    g_count;
// weights, [N][K] K-major rows, fp16. g_W3P = pair-summed W3 (K=256!)
__device__ __align__(256) __half g_W3P[DD*DD];
__device__ __align__(256) __half g_W1T[DD*DD];
__device__ __align__(256) __half g_W2T[DD*DD];
__device__ __align__(256) __half g_W4T[DD*DD];
__device__ __align__(256) __half g_W5T[DD*DD];

__device__ __forceinline__ void mma_f16(float* c, const uint32_t* a, const uint32_t* b) {
    asm volatile(
        "mma.sync.aligned.m16n8k16.row.col.f32.f16.f16.f32 "
        "{%0,%1,%2,%3}, {%4,%5,%6,%7}, {%8,%9}, {%0,%1,%2,%3};"
        : "+f"(c[0]), "+f"(c[1]), "+f"(c[2]), "+f"(c[3])
        : "r"(a[0]), "r"(a[1]), "r"(a[2]), "r"(a[3]), "r"(b[0]), "r"(b[1]));
}
__device__ __forceinline__ void ldsm4(uint32_t* r, uint32_t addr) {
    asm volatile("ldmatrix.sync.aligned.m8n8.x4.shared.b16 {%0,%1,%2,%3}, [%4];"
        : "=r"(r[0]), "=r"(r[1]), "=r"(r[2]), "=r"(r[3]) : "r"(addr));
}
__device__ __forceinline__ uint32_t smem_u32(const void* p) {
    uint32_t a;
    asm("{ .reg .u64 t; cvta.to.shared.u64 t, %1; cvt.u32.u64 %0, t; }" : "=r"(a) : "l"(p));
    return a;
}
__device__ __forceinline__ uint32_t packh2(float a, float b) {
    __half2 h = __floats2half2_rn(a, b);
    return *(uint32_t*)&h;
}
#define CP16(dst, src) asm volatile("cp.async.cg.shared.global [%0], [%1], 16;" :: "r"(dst), "l"(src))
#define CP_COMMIT()    asm volatile("cp.async.commit_group;" ::: "memory")
#define CP_WAIT0()     asm volatile("cp.async.wait_group 0;" ::: "memory")

// ---------------- smem layout, parameterized on BM --------------------------
#define PADH 40        /* staged tile row stride, fp16 */
#define HSTR 264       /* H-tile row stride, fp16 */
template<int BM> struct Lay {
    static constexpr int SA  = 0;
    static constexpr int SAB = BM*PADH*2;
    static constexpr int SB  = 2*SAB;
    static constexpr int SBB = 256*PADH*2;           /* 20480 */
    static constexpr int SH  = SB + 2*SBB;
    static constexpr int SHB = BM*HSTR*2;
    static constexpr int C0  = SH + SHB;
    static constexpr int C1  = C0 + 1024;
    static constexpr int C2  = C1 + 1024;
    static constexpr int PM  = C2 + 1024;
    static constexpr int W   = PM + BM*16;
    static constexpr int CF  = W + BM*4;
    static constexpr int SZ  = CF + 256;
};
// Lay<128>::SZ = 134912 (1 CTA/SM); Lay<64>::SZ = 89600 (2 CTAs/SM)

// ---------------- prep (merged): W3P + transposes + s64 + counter -----------
__global__ void k_prep(const float* __restrict__ W1, const float* __restrict__ W2,
                       const float* __restrict__ W3, const float* __restrict__ W4,
                       const float* __restrict__ W5) {
    int bid = blockIdx.x, tid = threadIdx.x;
    if (bid < 256) {
        // W3P[n][k'] = W3[64+j0][n] + W3[64+j0+1][n];  k'=(a,sf,m): a=k'>>7,
        // sf=(k'>>6)&1, m=k'&63; j0 = a*256+sf*128+2m
        int idx = bid*256 + tid;
        int n = idx >> 8, kp = idx & 255;
        int a = kp >> 7, sf = (kp >> 6) & 1, m = kp & 63;
        int j0 = a*256 + sf*128 + 2*m;
        float s = W3[(size_t)(64 + j0)*DD + n] + W3[(size_t)(65 + j0)*DD + n];
        g_W3P[n*DD + kp] = __float2half(s);
    } else if (bid < 1280) {
        int r = (bid - 256)*256 + tid;
        int mm = r >> 16, e = r & 65535;
        int n = e >> 8, k = e & 255;
        if      (mm == 0) g_W1T[e] = __float2half(W1[(size_t)k*DD + n]);
        else if (mm == 1) g_W2T[e] = __float2half(W2[(size_t)k*DD + n]);
        else if (mm == 2) g_W4T[e] = __float2half(W4[(size_t)k*DD + n]);
        else              g_W5T[e] = __float2half(W5[(size_t)k*DD + n]);
    } else {
        float s = 0.f;
        #pragma unroll 8
        for (int r = 0; r < 64; r++) s += W3[r*DD + tid];
        g_s64[tid] = s;
        if (tid == 0) g_count = 0;
    }
}

// ---------------- top-K: one warp per row, register-resident ----------------
#define NU 29
__global__ __launch_bounds__(256)
void k_topk(const float* __restrict__ ious,
            const float* __restrict__ gmask,
            const float* __restrict__ bboxes) {
    int wid = threadIdx.x >> 5, lid = threadIdx.x & 31;
    int r = blockIdx.x * 8 + wid;
    if (r >= ROWS) return;
    int b = r / NQ, i = r % NQ;
    const float* Mrow = gmask + b*NQ;
    float neg_i = 1.0f - Mrow[i];
    if (neg_i == 0.0f) {
        if (lid == 0) { g_rowbase[r] = 0; g_rowcnt[r] = 0; }
        return;
    }
    const float* irow = ious + (size_t)r * NQ;
    float ov[NU];
    #pragma unroll
    for (int u = 0; u < NU; u++) {
        int j = lid + u*32;
        ov[u] = (j < NQ) ? irow[j] * Mrow[j] * neg_i : -3.4e38f;
    }
    float kv[KK]; int ki[KK];
    float lastv = 3.5e38f; int lasti = -1;
    #pragma unroll
    for (int t = 0; t < KK; t++) {
        float lv = -3.4e38f; int li = NQ;
        #pragma unroll
        for (int u = 0; u < NU; u++) {
            int j = lid + u*32;
            float v = ov[u];
            bool inc = (v < lastv) || (v == lastv && j > lasti);
            if (inc && (v > lv || (v == lv && j < li))) { lv = v; li = j; }
        }
        #pragma unroll
        for (int off = 16; off > 0; off >>= 1) {
            float vv = __shfl_xor_sync(0xffffffffu, lv, off);
            int   ii = __shfl_xor_sync(0xffffffffu, li, off);
            if (vv > lv || (vv == lv && ii < li)) { lv = vv; li = ii; }
        }
        kv[t] = lv; ki[t] = li;
        lastv = lv; lasti = li;
    }
    if (lid == 0) {
        float mkv[KK];
        int cnt = 0;
        #pragma unroll
        for (int t = 0; t < KK; t++) {
            float nmk = Mrow[ki[t]];
            float mk  = (kv[t] >= 0.4f) ? nmk : 0.0f;
            mkv[t] = mk;
            if (mk != 0.0f) cnt++;
        }
        int base = (cnt > 0) ? atomicAdd(&g_count, cnt) : 0;
        g_rowbase[r] = base; g_rowcnt[r] = cnt;

        const float* cb = bboxes + (size_t)r * 4;
        float ccx = 0.5f*(cb[0]+cb[2]), ccy = 0.5f*(cb[1]+cb[3]);
        float cw = cb[2]-cb[0], ch = cb[3]-cb[1];
        int s = 0;
        #pragma unroll
        for (int t = 0; t < KK; t++) {
            if (mkv[t] == 0.0f) continue;
            const float* nb = bboxes + (size_t)(b*NQ + ki[t]) * 4;
            float dcx = 0.5f*(nb[0]+nb[2]) - ccx;
            float dcy = 0.5f*(nb[1]+nb[3]) - ccy;
            float dw  = (nb[2]-nb[0]) - cw;
            float dh  = (nb[3]-nb[1]) - ch;
            float4 pm;
            pm.x = logf(fmaxf(fabsf(dcx), 1e-7f));
            pm.y = logf(fmaxf(fabsf(dcy), 1e-7f));
            pm.z = logf(fmaxf(fabsf(dw ), 1e-7f));
            pm.w = logf(fmaxf(fabsf(dh ), 1e-7f));
            g_pm[base+s]    = pm;
            g_w[base+s]     = neg_i * Mrow[ki[t]] * mkv[t];
            g_oval[base+s]  = kv[t] * mkv[t];
            g_mkval[base+s] = mkv[t];
            s++;
        }
    }
}

// ---------------- GEMM phase helpers (NT = 4*BM threads, warp 64x32) --------
__device__ __forceinline__ void zero_acc(float acc[4][4][4]) {
    #pragma unroll
    for (int m = 0; m < 4; m++)
        #pragma unroll
        for (int n = 0; n < 4; n++)
            #pragma unroll
            for (int q = 0; q < 4; q++) acc[m][n][q] = 0.f;
}

__device__ __forceinline__ void mma_chunk(uint32_t aab, uint32_t bbb, int astr,
                                          float acc[4][4][4]) {
    #pragma unroll
    for (int kb = 0; kb < 32; kb += 16) {
        uint32_t af[4][4], bq[2][4];
        #pragma unroll
        for (int m = 0; m < 4; m++)
            ldsm4(af[m], aab + (uint32_t)((m*16*astr + kb) * 2));
        #pragma unroll
        for (int g = 0; g < 2; g++)
            ldsm4(bq[g], bbb + (uint32_t)((g*16*PADH + kb) * 2));
        #pragma unroll
        for (int m = 0; m < 4; m++) {
            #pragma unroll
            for (int n = 0; n < 4; n++) {
                uint32_t bfr[2] = { bq[n>>1][n&1], bq[n>>1][(n&1)+2] };
                mma_f16(acc[m][n], af[m], bfr);
            }
        }
    }
}

template<int BM, int KD, class F>
__device__ __forceinline__ void phase_staged(
    const __half* __restrict__ WT, char* smem,
    uint32_t aaddr, uint32_t baddr, uint32_t Bsm_b,
    int tid, F fill, float acc[4][4][4]) {
    using L = Lay<BM>;
    constexpr int NT = 4*BM;
    zero_acc(acc);
    const int s_row = tid >> 2, s_q = tid & 3;
    auto issueB = [&](int c, int buf) {
        #pragma unroll
        for (int i = 0; i < 1024/NT; i++) {
            int f = tid + i*NT;
            int row = f >> 2, q = f & 3;
            uint32_t dst = Bsm_b + buf*L::SBB + (uint32_t)(row*PADH*2 + q*16);
            CP16(dst, WT + (size_t)row*KD + c*32 + q*8);
        }
    };
    auto storeA = [&](int buf, uint4 v) {
        *(uint4*)(smem + L::SA + buf*L::SAB + (s_row*PADH + s_q*8)*2) = v;
    };
    issueB(0, 0); CP_COMMIT();
    storeA(0, fill(0));
    CP_WAIT0(); __syncthreads();
    const int nc = KD / 32;
    for (int c = 0; c < nc; c++) {
        int buf = c & 1;
        bool pf = (c + 1 < nc);
        uint4 nv;
        if (pf) { issueB(c+1, buf^1); CP_COMMIT(); nv = fill(c+1); }
        mma_chunk(aaddr + buf*L::SAB, baddr + buf*L::SBB, PADH, acc);
        if (pf) { storeA(buf^1, nv); CP_WAIT0(); }
        __syncthreads();
    }
}

template<int BM>
__device__ __forceinline__ void phase_smemA(
    const __half* __restrict__ WT,
    uint32_t haddr, uint32_t baddr, uint32_t Bsm_b,
    int tid, float acc[4][4][4]) {
    using L = Lay<BM>;
    constexpr int NT = 4*BM;
    zero_acc(acc);
    auto issueB = [&](int c, int buf) {
        #pragma unroll
        for (int i = 0; i < 1024/NT; i++) {
            int f = tid + i*NT;
            int row = f >> 2, q = f & 3;
            uint32_t dst = Bsm_b + buf*L::SBB + (uint32_t)(row*PADH*2 + q*16);
            CP16(dst, WT + (size_t)row*DD + c*32 + q*8);
        }
    };
    issueB(0, 0); CP_COMMIT();
    CP_WAIT0(); __syncthreads();   // orders prior Hsm writes vs ldsm reads
    for (int c = 0; c < 8; c++) {
        int buf = c & 1;
        bool pf = (c + 1 < 8);
        if (pf) { issueB(c+1, buf^1); CP_COMMIT(); }
        mma_chunk(haddr + (uint32_t)(c*32*2), baddr + buf*L::SBB, HSTR, acc);
        if (pf) { CP_WAIT0(); }
        __syncthreads();
    }
}

// ---------------- fused MG: H = relu(wave_half@W3P+b3+ovl*s64); feat=H@W4 ---
__global__ __launch_bounds__(512, 1)
void k_mg(const float* __restrict__ b3, const float* __restrict__ b4) {
    using L = Lay<128>;
    extern __shared__ __align__(16) char smem[];
    float*  bias3_s = (float*)(smem + L::C0);
    float*  s64_s   = (float*)(smem + L::C1);
    float*  bias4_s = (float*)(smem + L::C2);
    float4* pm_s    = (float4*)(smem + L::PM);
    float*  w_s     = (float*)(smem + L::W);
    float*  coef_s  = (float*)(smem + L::CF);

    int M = g_count;
    int m0 = blockIdx.x * 128;
    if (m0 >= M) return;

    int tid = threadIdx.x, wid = tid >> 5, lid = tid & 31;
    int gid = lid >> 2, ti = lid & 3;
    int warpM = wid & 1, warpN = wid >> 1;     // 16 warps: 2M x 8N, tile 64x32
    int l16 = lid & 15, lk = (lid >> 4) * 8;

    if (tid < 256) { bias3_s[tid] = b3[tid]; s64_s[tid] = g_s64[tid]; bias4_s[tid] = b4[tid]; }
    else if (tid < 384) {
        int rr = m0 + tid - 256;
        if (rr < M) { pm_s[tid-256] = g_pm[rr]; w_s[tid-256] = g_w[rr]; }
        else { pm_s[tid-256] = make_float4(0.f,0.f,0.f,0.f); w_s[tid-256] = 0.f; }
    } else if (tid < 448) {
        coef_s[tid-384] = 6.2831853071795865f *
                          exp2f(-(float)(tid-384) * (13.287712379549450f/64.f));
    }
    __syncthreads();

    uint32_t Asm_b = smem_u32(smem + L::SA);
    uint32_t Bsm_b = smem_u32(smem + L::SB);
    uint32_t Hsm_b = smem_u32(smem + L::SH);
    uint32_t aaddr = Asm_b + (uint32_t)((warpM*64 + l16) * PADH + lk) * 2u;
    uint32_t baddr = Bsm_b + (uint32_t)((warpN*32 + l16) * PADH + lk) * 2u;
    uint32_t haddr = Hsm_b + (uint32_t)((warpM*64 + l16) * HSTR + lk) * 2u;

    float acc[4][4][4];

    // ---- phase 1: wave_half @ W3P (K=256), A generated on the fly ----
    {
        const int s_row = tid >> 2, s_q = tid & 3;
        float4 pm = pm_s[s_row]; float wv = w_s[s_row];
        auto fill = [&](int c) -> uint4 {
            const float* pmp = (const float*)&pm;
            uint32_t h[4];
            #pragma unroll
            for (int p = 0; p < 4; p++) {
                float v[2];
                #pragma unroll
                for (int e = 0; e < 2; e++) {
                    int k = c*32 + s_q*8 + 2*p + e;
                    int a = k >> 7, sf = (k >> 6) & 1, m = k & 63;
                    float ang = coef_s[m] * pmp[2*a + sf];
                    v[e] = (sf ? __cosf(ang) : __sinf(ang)) * wv;
                }
                h[p] = packh2(v[0], v[1]);
            }
            return make_uint4(h[0], h[1], h[2], h[3]);
        };
        phase_staged<128, DD>(g_W3P, smem, aaddr, baddr, Bsm_b, tid, fill, acc);
    }

    // ---- epilogue 1: H into Hsm (fp16) ----
    __half* Hsm = (__half*)(smem + L::SH);
    #pragma unroll
    for (int m = 0; m < 4; m++) {
        int rl0 = warpM*64 + m*16 + gid;
        #pragma unroll
        for (int h = 0; h < 2; h++) {
            int rl = rl0 + h*8;
            int rg = m0 + rl;
            float ovl = (rg < M) ? g_oval[rg] : 0.f;
            #pragma unroll
            for (int n = 0; n < 4; n++) {
                int lc = warpN*32 + n*8 + ti*2;
                float v0 = fmaxf(acc[m][n][h*2+0] + bias3_s[lc]   + ovl*s64_s[lc],   0.f);
                float v1 = fmaxf(acc[m][n][h*2+1] + bias3_s[lc+1] + ovl*s64_s[lc+1], 0.f);
                *(__half2*)(Hsm + rl*HSTR + lc) = __floats2half2_rn(v0, v1);
            }
        }
    }
    __syncthreads();

    // ---- phase 2: H @ W4T (K=256) ----
    phase_smemA<128>(g_W4T, haddr, baddr, Bsm_b, tid, acc);

    // ---- epilogue 2: feat (fp32) to global ----
    #pragma unroll
    for (int m = 0; m < 4; m++) {
        int rl0 = warpM*64 + m*16 + gid;
        #pragma unroll
        for (int h = 0; h < 2; h++) {
            int rg = m0 + rl0 + h*8;
            if (rg >= M) continue;
            #pragma unroll
            for (int n = 0; n < 4; n++) {
                int lc = warpN*32 + n*8 + ti*2;
                float v0 = acc[m][n][h*2+0] + bias4_s[lc];
                float v1 = acc[m][n][h*2+1] + bias4_s[lc+1];
                *(float2*)(g_feat + (size_t)rg*DD + lc) = make_float2(v0, v1);
            }
        }
    }
}

// ---------------- masked max over K neighbors -------------------------------
__global__ void k_reduce() {
    int r = blockIdx.x, d = threadIdx.x;
    int base = g_rowbase[r], cnt = g_rowcnt[r];
    float m = (cnt < KK) ? 0.0f : -3.4e38f;
    for (int e = 0; e < cnt; e++)
        m = fmaxf(m, g_mkval[base+e] * g_feat[(size_t)(base+e)*DD + d]);
    g_agg[(size_t)r*DD + d] = m;
}

// ---------------- fused query chain: T1 -> Z -> out (BM=64, 2 CTAs/SM) ------
__global__ __launch_bounds__(256, 2)
void k_q(const float* __restrict__ tgt, const float* __restrict__ gmask,
         const float* __restrict__ b1, const float* __restrict__ b2,
         const float* __restrict__ b5, float* __restrict__ out) {
    using L = Lay<64>;
    extern __shared__ __align__(16) char smem[];
    float* bias1_s = (float*)(smem + L::C0);
    float* bias2_s = (float*)(smem + L::C1);
    float* bias5_s = (float*)(smem + L::C2);

    const int M = ROWS;
    int m0 = blockIdx.x * 64;
    if (m0 >= M) return;

    int tid = threadIdx.x, wid = tid >> 5, lid = tid & 31;
    int gid = lid >> 2, ti = lid & 3;
    int warpN = wid;                          // 8 warps, warp tile 64x32
    int l16 = lid & 15, lk = (lid >> 4) * 8;

    bias1_s[tid] = b1[tid]; bias2_s[tid] = b2[tid]; bias5_s[tid] = b5[tid];
    __syncthreads();

    uint32_t Asm_b = smem_u32(smem + L::SA);
    uint32_t Bsm_b = smem_u32(smem + L::SB);
    uint32_t Hsm_b = smem_u32(smem + L::SH);
    uint32_t aaddr = Asm_b + (uint32_t)(l16 * PADH + lk) * 2u;
    uint32_t baddr = Bsm_b + (uint32_t)((warpN*32 + l16) * PADH + lk) * 2u;
    uint32_t haddr = Hsm_b + (uint32_t)(l16 * HSTR + lk) * 2u;
    __half* Hsm = (__half*)(smem + L::SH);

    float acc[4][4][4];

    // ---- phase 1: relu(tgt @ W1T + b1) -> Hsm ----
    {
        const int s_row = tid >> 2, s_q = tid & 3;
        auto fill = [&](int c) -> uint4 {
            int gr = m0 + s_row;
            float4 f0 = make_float4(0.f,0.f,0.f,0.f), f1 = f0;
            if (gr < M) {
                const float* ap = tgt + (size_t)gr*DD + c*32 + s_q*8;
                f0 = *(const float4*)ap; f1 = *(const float4*)(ap + 4);
            }
            return make_uint4(packh2(f0.x,f0.y), packh2(f0.z,f0.w),
                              packh2(f1.x,f1.y), packh2(f1.z,f1.w));
        };
        phase_staged<64, DD>(g_W1T, smem, aaddr, baddr, Bsm_b, tid, fill, acc);
    }
    #pragma unroll
    for (int m = 0; m < 4; m++) {
        int rl0 = m*16 + gid;
        #pragma unroll
        for (int h = 0; h < 2; h++) {
            int rl = rl0 + h*8;
            #pragma unroll
            for (int n = 0; n < 4; n++) {
                int lc = warpN*32 + n*8 + ti*2;
                float v0 = fmaxf(acc[m][n][h*2+0] + bias1_s[lc],   0.f);
                float v1 = fmaxf(acc[m][n][h*2+1] + bias1_s[lc+1], 0.f);
                *(__half2*)(Hsm + rl*HSTR + lc) = __floats2half2_rn(v0, v1);
            }
        }
    }
    __syncthreads();

    // ---- phase 2: Z = (T1 @ W2T + b2)*neg + agg -> Hsm ----
    phase_smemA<64>(g_W2T, haddr, baddr, Bsm_b, tid, acc);
    #pragma unroll
    for (int m = 0; m < 4; m++) {
        int rl0 = m*16 + gid;
        #pragma unroll
        for (int h = 0; h < 2; h++) {
            int rl = rl0 + h*8;
            int rg = m0 + rl;
            if (rg >= M) continue;
            float ng = 1.f - gmask[rg];
            const float* ar = g_agg + (size_t)rg*DD;
            #pragma unroll
            for (int n = 0; n < 4; n++) {
                int lc = warpN*32 + n*8 + ti*2;
                float v0 = (acc[m][n][h*2+0] + bias2_s[lc])   * ng + ar[lc];
                float v1 = (acc[m][n][h*2+1] + bias2_s[lc+1]) * ng + ar[lc+1];
                *(__half2*)(Hsm + rl*HSTR + lc) = __floats2half2_rn(v0, v1);
            }
        }
    }
    __syncthreads();

    // ---- phase 3: out = relu(Z @ W5T + b5) * neg ----
    phase_smemA<64>(g_W5T, haddr, baddr, Bsm_b, tid, acc);
    #pragma unroll
    for (int m = 0; m < 4; m++) {
        int rl0 = m*16 + gid;
        #pragma unroll
        for (int h = 0; h < 2; h++) {
            int rg = m0 + rl0 + h*8;
            if (rg >= M) continue;
            float ng = 1.f - gmask[rg];
            #pragma unroll
            for (int n = 0; n < 4; n++) {
                int lc = warpN*32 + n*8 + ti*2;
                float v0 = fmaxf(acc[m][n][h*2+0] + bias5_s[lc],   0.f) * ng;
                float v1 = fmaxf(acc[m][n][h*2+1] + bias5_s[lc+1], 0.f) * ng;
                *(float2*)(out + (size_t)rg*DD + lc) = make_float2(v0, v1);
            }
        }
    }
}

// ---------------- launch ----------------------------------------------------
extern "C" void kernel_launch(void* const* d_in, const int* in_sizes, int n_in,
                              void* d_out, int out_size) {
    const float* tgt    = (const float*)d_in[0];
    const float* ious   = (const float*)d_in[1];
    const float* bboxes = (const float*)d_in[2];
    const float* gmask  = (const float*)d_in[3];
    const float* W1 = (const float*)d_in[4];  const float* b1 = (const float*)d_in[5];
    const float* W2 = (const float*)d_in[6];  const float* b2 = (const float*)d_in[7];
    const float* W3 = (const float*)d_in[8];  const float* b3 = (const float*)d_in[9];
    const float* W4 = (const float*)d_in[10]; const float* b4 = (const float*)d_in[11];
    const float* W5 = (const float*)d_in[12]; const float* b5 = (const float*)d_in[13];
    float* out = (float*)d_out;

    cudaFuncSetAttribute(k_mg, cudaFuncAttributeMaxDynamicSharedMemorySize, Lay<128>::SZ);
    cudaFuncSetAttribute(k_q,  cudaFuncAttributeMaxDynamicSharedMemorySize, Lay<64>::SZ);

    k_prep<<<1281, 256>>>(W1, W2, W3, W4, W5);
    k_topk<<<(ROWS + 7) / 8, 256>>>(ious, gmask, bboxes);

    k_mg<<<(FMAX + 127) / 128, 512, Lay<128>::SZ>>>(b3, b4);
    k_reduce<<<ROWS, DD>>>();
    k_q<<<(ROWS + 63) / 64, 256, Lay<64>::SZ>>>(tgt, gmask, b1, b2, b5, out);
}

// round 13
// speedup vs baseline: 1.7412x; 1.1477x over previous
#include <cuda_runtime.h>
#include <cuda_fp16.h>
#include <math.h>
#include <stdint.h>

#define BSZ 8
#define NQ 900
#define DD 256
#define KK 10
#define ROWS (BSZ*NQ)        /* 7200  */
#define FMAX (ROWS*KK)       /* 72000 */
#define WDIM 512

// ---------------- scratch (static __device__ arrays; no allocation) ----------
__device__ __align__(256) float4 g_pm[FMAX];
__device__ __align__(256) float  g_w[FMAX];
__device__ __align__(256) float  g_oval[FMAX];
__device__ __align__(256) float  g_mkval[FMAX];
__device__ __align__(256) __half g_feat[(size_t)FMAX*DD];   // fused MG output, fp16
__device__ int    g_rowbase[ROWS];
__device__ int    g_rowcnt[ROWS];
__device__ __align__(256) float  g_agg[(size_t)ROWS*DD];
__device__ float  g_s64[DD];
__device__ int    g_count;
// weights, [N][K] K-major rows, fp16. g_W3P = pair-summed W3 (K=256!)
__device__ __align__(256) __half g_W3P[DD*DD];
__device__ __align__(256) __half g_W1T[DD*DD];
__device__ __align__(256) __half g_W2T[DD*DD];
__device__ __align__(256) __half g_W4T[DD*DD];
__device__ __align__(256) __half g_W5T[DD*DD];

__device__ __forceinline__ void mma_f16(float* c, const uint32_t* a, const uint32_t* b) {
    asm volatile(
        "mma.sync.aligned.m16n8k16.row.col.f32.f16.f16.f32 "
        "{%0,%1,%2,%3}, {%4,%5,%6,%7}, {%8,%9}, {%0,%1,%2,%3};"
        : "+f"(c[0]), "+f"(c[1]), "+f"(c[2]), "+f"(c[3])
        : "r"(a[0]), "r"(a[1]), "r"(a[2]), "r"(a[3]), "r"(b[0]), "r"(b[1]));
}
__device__ __forceinline__ void ldsm4(uint32_t* r, uint32_t addr) {
    asm volatile("ldmatrix.sync.aligned.m8n8.x4.shared.b16 {%0,%1,%2,%3}, [%4];"
        : "=r"(r[0]), "=r"(r[1]), "=r"(r[2]), "=r"(r[3]) : "r"(addr));
}
__device__ __forceinline__ uint32_t smem_u32(const void* p) {
    uint32_t a;
    asm("{ .reg .u64 t; cvta.to.shared.u64 t, %1; cvt.u32.u64 %0, t; }" : "=r"(a) : "l"(p));
    return a;
}
__device__ __forceinline__ uint32_t packh2(float a, float b) {
    __half2 h = __floats2half2_rn(a, b);
    return *(uint32_t*)&h;
}
#define CP16(dst, src) asm volatile("cp.async.cg.shared.global [%0], [%1], 16;" :: "r"(dst), "l"(src))
#define CP_COMMIT()    asm volatile("cp.async.commit_group;" ::: "memory")
#define CP_WAIT0()     asm volatile("cp.async.wait_group 0;" ::: "memory")

// ---------------- smem layout, parameterized on BM --------------------------
#define PADH 40        /* staged tile row stride, fp16 */
#define HSTR 264       /* H-tile row stride, fp16 */
template<int BM> struct Lay {
    static constexpr int SA  = 0;
    static constexpr int SAB = BM*PADH*2;
    static constexpr int SB  = 2*SAB;
    static constexpr int SBB = 256*PADH*2;           /* 20480 */
    static constexpr int SH  = SB + 2*SBB;
    static constexpr int SHB = BM*HSTR*2;
    static constexpr int C0  = SH + SHB;
    static constexpr int C1  = C0 + 1024;
    static constexpr int C2  = C1 + 1024;
    static constexpr int PM  = C2 + 1024;
    static constexpr int W   = PM + BM*16;
    static constexpr int CF  = W + BM*4;
    static constexpr int SZ  = CF + 256;
};
// Lay<128>::SZ = 134912 (1 CTA/SM); Lay<64>::SZ = 89600 (2 CTAs/SM)

// ---------------- prep (merged): W3P + transposes + s64 + counter -----------
__global__ void k_prep(const float* __restrict__ W1, const float* __restrict__ W2,
                       const float* __restrict__ W3, const float* __restrict__ W4,
                       const float* __restrict__ W5) {
    int bid = blockIdx.x, tid = threadIdx.x;
    if (bid < 256) {
        // W3P[n][kp] = W3[64+j0][n] + W3[64+j0+1][n]; kp=bid (fixed per block),
        // n=tid -> both W3 row reads coalesced. kp=(a,sf,m): a=kp>>7,
        // sf=(kp>>6)&1, m=kp&63; j0 = a*256+sf*128+2m
        int kp = bid, n = tid;
        int a = kp >> 7, sf = (kp >> 6) & 1, m = kp & 63;
        int j0 = a*256 + sf*128 + 2*m;
        float s = W3[(size_t)(64 + j0)*DD + n] + W3[(size_t)(65 + j0)*DD + n];
        g_W3P[n*DD + kp] = __float2half(s);
    } else if (bid < 1280) {
        int r = (bid - 256)*256 + tid;
        int mm = r >> 16, e = r & 65535;
        int n = e >> 8, k = e & 255;
        if      (mm == 0) g_W1T[e] = __float2half(W1[(size_t)k*DD + n]);
        else if (mm == 1) g_W2T[e] = __float2half(W2[(size_t)k*DD + n]);
        else if (mm == 2) g_W4T[e] = __float2half(W4[(size_t)k*DD + n]);
        else              g_W5T[e] = __float2half(W5[(size_t)k*DD + n]);
    } else {
        float s = 0.f;
        #pragma unroll 8
        for (int r = 0; r < 64; r++) s += W3[r*DD + tid];
        g_s64[tid] = s;
        if (tid == 0) g_count = 0;
    }
}

// ---------------- top-K: one warp per row, register-resident ----------------
#define NU 29
__global__ __launch_bounds__(256)
void k_topk(const float* __restrict__ ious,
            const float* __restrict__ gmask,
            const float* __restrict__ bboxes) {
    int wid = threadIdx.x >> 5, lid = threadIdx.x & 31;
    int r = blockIdx.x * 8 + wid;
    if (r >= ROWS) return;
    int b = r / NQ, i = r % NQ;
    const float* Mrow = gmask + b*NQ;
    float neg_i = 1.0f - Mrow[i];
    if (neg_i == 0.0f) {
        if (lid == 0) { g_rowbase[r] = 0; g_rowcnt[r] = 0; }
        return;
    }
    const float* irow = ious + (size_t)r * NQ;
    float ov[NU];
    #pragma unroll
    for (int u = 0; u < NU; u++) {
        int j = lid + u*32;
        ov[u] = (j < NQ) ? irow[j] * Mrow[j] * neg_i : -3.4e38f;
    }
    float kv[KK]; int ki[KK];
    float lastv = 3.5e38f; int lasti = -1;
    #pragma unroll
    for (int t = 0; t < KK; t++) {
        float lv = -3.4e38f; int li = NQ;
        #pragma unroll
        for (int u = 0; u < NU; u++) {
            int j = lid + u*32;
            float v = ov[u];
            bool inc = (v < lastv) || (v == lastv && j > lasti);
            if (inc && (v > lv || (v == lv && j < li))) { lv = v; li = j; }
        }
        #pragma unroll
        for (int off = 16; off > 0; off >>= 1) {
            float vv = __shfl_xor_sync(0xffffffffu, lv, off);
            int   ii = __shfl_xor_sync(0xffffffffu, li, off);
            if (vv > lv || (vv == lv && ii < li)) { lv = vv; li = ii; }
        }
        kv[t] = lv; ki[t] = li;
        lastv = lv; lasti = li;
    }
    if (lid == 0) {
        float mkv[KK];
        int cnt = 0;
        #pragma unroll
        for (int t = 0; t < KK; t++) {
            float nmk = Mrow[ki[t]];
            float mk  = (kv[t] >= 0.4f) ? nmk : 0.0f;
            mkv[t] = mk;
            if (mk != 0.0f) cnt++;
        }
        int base = (cnt > 0) ? atomicAdd(&g_count, cnt) : 0;
        g_rowbase[r] = base; g_rowcnt[r] = cnt;

        const float* cb = bboxes + (size_t)r * 4;
        float ccx = 0.5f*(cb[0]+cb[2]), ccy = 0.5f*(cb[1]+cb[3]);
        float cw = cb[2]-cb[0], ch = cb[3]-cb[1];
        int s = 0;
        #pragma unroll
        for (int t = 0; t < KK; t++) {
            if (mkv[t] == 0.0f) continue;
            const float* nb = bboxes + (size_t)(b*NQ + ki[t]) * 4;
            float dcx = 0.5f*(nb[0]+nb[2]) - ccx;
            float dcy = 0.5f*(nb[1]+nb[3]) - ccy;
            float dw  = (nb[2]-nb[0]) - cw;
            float dh  = (nb[3]-nb[1]) - ch;
            float4 pm;
            pm.x = logf(fmaxf(fabsf(dcx), 1e-7f));
            pm.y = logf(fmaxf(fabsf(dcy), 1e-7f));
            pm.z = logf(fmaxf(fabsf(dw ), 1e-7f));
            pm.w = logf(fmaxf(fabsf(dh ), 1e-7f));
            g_pm[base+s]    = pm;
            g_w[base+s]     = neg_i * Mrow[ki[t]] * mkv[t];
            g_oval[base+s]  = kv[t] * mkv[t];
            g_mkval[base+s] = mkv[t];
            s++;
        }
    }
}

// ---------------- GEMM phase helpers (NT = 4*BM threads, warp 64x32) --------
__device__ __forceinline__ void zero_acc(float acc[4][4][4]) {
    #pragma unroll
    for (int m = 0; m < 4; m++)
        #pragma unroll
        for (int n = 0; n < 4; n++)
            #pragma unroll
            for (int q = 0; q < 4; q++) acc[m][n][q] = 0.f;
}

__device__ __forceinline__ void mma_chunk(uint32_t aab, uint32_t bbb, int astr,
                                          float acc[4][4][4]) {
    #pragma unroll
    for (int kb = 0; kb < 32; kb += 16) {
        uint32_t af[4][4], bq[2][4];
        #pragma unroll
        for (int m = 0; m < 4; m++)
            ldsm4(af[m], aab + (uint32_t)((m*16*astr + kb) * 2));
        #pragma unroll
        for (int g = 0; g < 2; g++)
            ldsm4(bq[g], bbb + (uint32_t)((g*16*PADH + kb) * 2));
        #pragma unroll
        for (int m = 0; m < 4; m++) {
            #pragma unroll
            for (int n = 0; n < 4; n++) {
                uint32_t bfr[2] = { bq[n>>1][n&1], bq[n>>1][(n&1)+2] };
                mma_f16(acc[m][n], af[m], bfr);
            }
        }
    }
}

template<int BM, int KD, class F>
__device__ __forceinline__ void phase_staged(
    const __half* __restrict__ WT, char* smem,
    uint32_t aaddr, uint32_t baddr, uint32_t Bsm_b,
    int tid, F fill, float acc[4][4][4]) {
    using L = Lay<BM>;
    constexpr int NT = 4*BM;
    zero_acc(acc);
    const int s_row = tid >> 2, s_q = tid & 3;
    auto issueB = [&](int c, int buf) {
        #pragma unroll
        for (int i = 0; i < 1024/NT; i++) {
            int f = tid + i*NT;
            int row = f >> 2, q = f & 3;
            uint32_t dst = Bsm_b + buf*L::SBB + (uint32_t)(row*PADH*2 + q*16);
            CP16(dst, WT + (size_t)row*KD + c*32 + q*8);
        }
    };
    auto storeA = [&](int buf, uint4 v) {
        *(uint4*)(smem + L::SA + buf*L::SAB + (s_row*PADH + s_q*8)*2) = v;
    };
    issueB(0, 0); CP_COMMIT();
    storeA(0, fill(0));
    CP_WAIT0(); __syncthreads();
    const int nc = KD / 32;
    for (int c = 0; c < nc; c++) {
        int buf = c & 1;
        bool pf = (c + 1 < nc);
        uint4 nv;
        if (pf) { issueB(c+1, buf^1); CP_COMMIT(); nv = fill(c+1); }
        mma_chunk(aaddr + buf*L::SAB, baddr + buf*L::SBB, PADH, acc);
        if (pf) { storeA(buf^1, nv); CP_WAIT0(); }
        __syncthreads();
    }
}

template<int BM>
__device__ __forceinline__ void phase_smemA(
    const __half* __restrict__ WT,
    uint32_t haddr, uint32_t baddr, uint32_t Bsm_b,
    int tid, float acc[4][4][4]) {
    using L = Lay<BM>;
    constexpr int NT = 4*BM;
    zero_acc(acc);
    auto issueB = [&](int c, int buf) {
        #pragma unroll
        for (int i = 0; i < 1024/NT; i++) {
            int f = tid + i*NT;
            int row = f >> 2, q = f & 3;
            uint32_t dst = Bsm_b + buf*L::SBB + (uint32_t)(row*PADH*2 + q*16);
            CP16(dst, WT + (size_t)row*DD + c*32 + q*8);
        }
    };
    issueB(0, 0); CP_COMMIT();
    CP_WAIT0(); __syncthreads();   // orders prior Hsm writes vs ldsm reads
    for (int c = 0; c < 8; c++) {
        int buf = c & 1;
        bool pf = (c + 1 < 8);
        if (pf) { issueB(c+1, buf^1); CP_COMMIT(); }
        mma_chunk(haddr + (uint32_t)(c*32*2), baddr + buf*L::SBB, HSTR, acc);
        if (pf) { CP_WAIT0(); }
        __syncthreads();
    }
}

// ---------------- fused MG: H = relu(wave_half@W3P+b3+ovl*s64); feat=H@W4 ---
__global__ __launch_bounds__(512, 1)
void k_mg(const float* __restrict__ b3, const float* __restrict__ b4) {
    using L = Lay<128>;
    extern __shared__ __align__(16) char smem[];
    float*  bias3_s = (float*)(smem + L::C0);
    float*  s64_s   = (float*)(smem + L::C1);
    float*  bias4_s = (float*)(smem + L::C2);
    float4* pm_s    = (float4*)(smem + L::PM);
    float*  w_s     = (float*)(smem + L::W);
    float*  coef_s  = (float*)(smem + L::CF);

    int M = g_count;
    int m0 = blockIdx.x * 128;
    if (m0 >= M) return;

    int tid = threadIdx.x, wid = tid >> 5, lid = tid & 31;
    int gid = lid >> 2, ti = lid & 3;
    int warpM = wid & 1, warpN = wid >> 1;     // 16 warps: 2M x 8N, tile 64x32
    int l16 = lid & 15, lk = (lid >> 4) * 8;

    if (tid < 256) { bias3_s[tid] = b3[tid]; s64_s[tid] = g_s64[tid]; bias4_s[tid] = b4[tid]; }
    else if (tid < 384) {
        int rr = m0 + tid - 256;
        if (rr < M) { pm_s[tid-256] = g_pm[rr]; w_s[tid-256] = g_w[rr]; }
        else { pm_s[tid-256] = make_float4(0.f,0.f,0.f,0.f); w_s[tid-256] = 0.f; }
    } else if (tid < 448) {
        coef_s[tid-384] = 6.2831853071795865f *
                          exp2f(-(float)(tid-384) * (13.287712379549450f/64.f));
    }
    __syncthreads();

    uint32_t Asm_b = smem_u32(smem + L::SA);
    uint32_t Bsm_b = smem_u32(smem + L::SB);
    uint32_t Hsm_b = smem_u32(smem + L::SH);
    uint32_t aaddr = Asm_b + (uint32_t)((warpM*64 + l16) * PADH + lk) * 2u;
    uint32_t baddr = Bsm_b + (uint32_t)((warpN*32 + l16) * PADH + lk) * 2u;
    uint32_t haddr = Hsm_b + (uint32_t)((warpM*64 + l16) * HSTR + lk) * 2u;

    float acc[4][4][4];

    // ---- phase 1: wave_half @ W3P (K=256), A generated on the fly ----
    {
        const int s_row = tid >> 2, s_q = tid & 3;
        float4 pm = pm_s[s_row]; float wv = w_s[s_row];
        auto fill = [&](int c) -> uint4 {
            const float* pmp = (const float*)&pm;
            uint32_t h[4];
            #pragma unroll
            for (int p = 0; p < 4; p++) {
                float v[2];
                #pragma unroll
                for (int e = 0; e < 2; e++) {
                    int k = c*32 + s_q*8 + 2*p + e;
                    int a = k >> 7, sf = (k >> 6) & 1, m = k & 63;
                    float ang = coef_s[m] * pmp[2*a + sf];
                    v[e] = (sf ? __cosf(ang) : __sinf(ang)) * wv;
                }
                h[p] = packh2(v[0], v[1]);
            }
            return make_uint4(h[0], h[1], h[2], h[3]);
        };
        phase_staged<128, DD>(g_W3P, smem, aaddr, baddr, Bsm_b, tid, fill, acc);
    }

    // ---- epilogue 1: H into Hsm (fp16) ----
    __half* Hsm = (__half*)(smem + L::SH);
    #pragma unroll
    for (int m = 0; m < 4; m++) {
        int rl0 = warpM*64 + m*16 + gid;
        #pragma unroll
        for (int h = 0; h < 2; h++) {
            int rl = rl0 + h*8;
            int rg = m0 + rl;
            float ovl = (rg < M) ? g_oval[rg] : 0.f;
            #pragma unroll
            for (int n = 0; n < 4; n++) {
                int lc = warpN*32 + n*8 + ti*2;
                float v0 = fmaxf(acc[m][n][h*2+0] + bias3_s[lc]   + ovl*s64_s[lc],   0.f);
                float v1 = fmaxf(acc[m][n][h*2+1] + bias3_s[lc+1] + ovl*s64_s[lc+1], 0.f);
                *(__half2*)(Hsm + rl*HSTR + lc) = __floats2half2_rn(v0, v1);
            }
        }
    }
    __syncthreads();

    // ---- phase 2: H @ W4T (K=256) ----
    phase_smemA<128>(g_W4T, haddr, baddr, Bsm_b, tid, acc);

    // ---- epilogue 2: feat (fp16) to global ----
    #pragma unroll
    for (int m = 0; m < 4; m++) {
        int rl0 = warpM*64 + m*16 + gid;
        #pragma unroll
        for (int h = 0; h < 2; h++) {
            int rg = m0 + rl0 + h*8;
            if (rg >= M) continue;
            #pragma unroll
            for (int n = 0; n < 4; n++) {
                int lc = warpN*32 + n*8 + ti*2;
                float v0 = acc[m][n][h*2+0] + bias4_s[lc];
                float v1 = acc[m][n][h*2+1] + bias4_s[lc+1];
                *(__half2*)(g_feat + (size_t)rg*DD + lc) = __floats2half2_rn(v0, v1);
            }
        }
    }
}

// ---------------- masked max over K neighbors (fp16 feat, half2 lanes) ------
__global__ __launch_bounds__(128)
void k_reduce() {
    int r = blockIdx.x, d = threadIdx.x;   // d: 0..127, handles dims 2d, 2d+1
    int base = g_rowbase[r], cnt = g_rowcnt[r];
    float floorv = (cnt < KK) ? 0.0f : -3.4e38f;
    float m0 = floorv, m1 = floorv;
    for (int e = 0; e < cnt; e++) {
        float mk = g_mkval[base+e];
        __half2 hv = *(const __half2*)(g_feat + (size_t)(base+e)*DD + 2*d);
        float2 fv = __half22float2(hv);
        m0 = fmaxf(m0, mk * fv.x);
        m1 = fmaxf(m1, mk * fv.y);
    }
    *(float2*)(g_agg + (size_t)r*DD + 2*d) = make_float2(m0, m1);
}

// ---------------- fused query chain: T1 -> Z -> out (BM=64, 2 CTAs/SM) ------
__global__ __launch_bounds__(256, 2)
void k_q(const float* __restrict__ tgt, const float* __restrict__ gmask,
         const float* __restrict__ b1, const float* __restrict__ b2,
         const float* __restrict__ b5, float* __restrict__ out) {
    using L = Lay<64>;
    extern __shared__ __align__(16) char smem[];
    float* bias1_s = (float*)(smem + L::C0);
    float* bias2_s = (float*)(smem + L::C1);
    float* bias5_s = (float*)(smem + L::C2);

    const int M = ROWS;
    int m0 = blockIdx.x * 64;
    if (m0 >= M) return;

    int tid = threadIdx.x, wid = tid >> 5, lid = tid & 31;
    int gid = lid >> 2, ti = lid & 3;
    int warpN = wid;                          // 8 warps, warp tile 64x32
    int l16 = lid & 15, lk = (lid >> 4) * 8;

    bias1_s[tid] = b1[tid]; bias2_s[tid] = b2[tid]; bias5_s[tid] = b5[tid];
    __syncthreads();

    uint32_t Asm_b = smem_u32(smem + L::SA);
    uint32_t Bsm_b = smem_u32(smem + L::SB);
    uint32_t Hsm_b = smem_u32(smem + L::SH);
    uint32_t aaddr = Asm_b + (uint32_t)(l16 * PADH + lk) * 2u;
    uint32_t baddr = Bsm_b + (uint32_t)((warpN*32 + l16) * PADH + lk) * 2u;
    uint32_t haddr = Hsm_b + (uint32_t)(l16 * HSTR + lk) * 2u;
    __half* Hsm = (__half*)(smem + L::SH);

    float acc[4][4][4];

    // ---- phase 1: relu(tgt @ W1T + b1) -> Hsm ----
    {
        const int s_row = tid >> 2, s_q = tid & 3;
        auto fill = [&](int c) -> uint4 {
            int gr = m0 + s_row;
            float4 f0 = make_float4(0.f,0.f,0.f,0.f), f1 = f0;
            if (gr < M) {
                const float* ap = tgt + (size_t)gr*DD + c*32 + s_q*8;
                f0 = *(const float4*)ap; f1 = *(const float4*)(ap + 4);
            }
            return make_uint4(packh2(f0.x,f0.y), packh2(f0.z,f0.w),
                              packh2(f1.x,f1.y), packh2(f1.z,f1.w));
        };
        phase_staged<64, DD>(g_W1T, smem, aaddr, baddr, Bsm_b, tid, fill, acc);
    }
    #pragma unroll
    for (int m = 0; m < 4; m++) {
        int rl0 = m*16 + gid;
        #pragma unroll
        for (int h = 0; h < 2; h++) {
            int rl = rl0 + h*8;
            #pragma unroll
            for (int n = 0; n < 4; n++) {
                int lc = warpN*32 + n*8 + ti*2;
                float v0 = fmaxf(acc[m][n][h*2+0] + bias1_s[lc],   0.f);
                float v1 = fmaxf(acc[m][n][h*2+1] + bias1_s[lc+1], 0.f);
                *(__half2*)(Hsm + rl*HSTR + lc) = __floats2half2_rn(v0, v1);
            }
        }
    }
    __syncthreads();

    // ---- phase 2: Z = (T1 @ W2T + b2)*neg + agg -> Hsm ----
    phase_smemA<64>(g_W2T, haddr, baddr, Bsm_b, tid, acc);
    #pragma unroll
    for (int m = 0; m < 4; m++) {
        int rl0 = m*16 + gid;
        #pragma unroll
        for (int h = 0; h < 2; h++) {
            int rl = rl0 + h*8;
            int rg = m0 + rl;
            if (rg >= M) continue;
            float ng = 1.f - gmask[rg];
            const float* ar = g_agg + (size_t)rg*DD;
            #pragma unroll
            for (int n = 0; n < 4; n++) {
                int lc = warpN*32 + n*8 + ti*2;
                float v0 = (acc[m][n][h*2+0] + bias2_s[lc])   * ng + ar[lc];
                float v1 = (acc[m][n][h*2+1] + bias2_s[lc+1]) * ng + ar[lc+1];
                *(__half2*)(Hsm + rl*HSTR + lc) = __floats2half2_rn(v0, v1);
            }
        }
    }
    __syncthreads();

    // ---- phase 3: out = relu(Z @ W5T + b5) * neg ----
    phase_smemA<64>(g_W5T, haddr, baddr, Bsm_b, tid, acc);
    #pragma unroll
    for (int m = 0; m < 4; m++) {
        int rl0 = m*16 + gid;
        #pragma unroll
        for (int h = 0; h < 2; h++) {
            int rg = m0 + rl0 + h*8;
            if (rg >= M) continue;
            float ng = 1.f - gmask[rg];
            #pragma unroll
            for (int n = 0; n < 4; n++) {
                int lc = warpN*32 + n*8 + ti*2;
                float v0 = fmaxf(acc[m][n][h*2+0] + bias5_s[lc],   0.f) * ng;
                float v1 = fmaxf(acc[m][n][h*2+1] + bias5_s[lc+1], 0.f) * ng;
                *(float2*)(out + (size_t)rg*DD + lc) = make_float2(v0, v1);
            }
        }
    }
}

// ---------------- launch ----------------------------------------------------
extern "C" void kernel_launch(void* const* d_in, const int* in_sizes, int n_in,
                              void* d_out, int out_size) {
    const float* tgt    = (const float*)d_in[0];
    const float* ious   = (const float*)d_in[1];
    const float* bboxes = (const float*)d_in[2];
    const float* gmask  = (const float*)d_in[3];
    const float* W1 = (const float*)d_in[4];  const float* b1 = (const float*)d_in[5];
    const float* W2 = (const float*)d_in[6];  const float* b2 = (const float*)d_in[7];
    const float* W3 = (const float*)d_in[8];  const float* b3 = (const float*)d_in[9];
    const float* W4 = (const float*)d_in[10]; const float* b4 = (const float*)d_in[11];
    const float* W5 = (const float*)d_in[12]; const float* b5 = (const float*)d_in[13];
    float* out = (float*)d_out;

    cudaFuncSetAttribute(k_mg, cudaFuncAttributeMaxDynamicSharedMemorySize, Lay<128>::SZ);
    cudaFuncSetAttribute(k_q,  cudaFuncAttributeMaxDynamicSharedMemorySize, Lay<64>::SZ);

    k_prep<<<1281, 256>>>(W1, W2, W3, W4, W5);
    k_topk<<<(ROWS + 7) / 8, 256>>>(ious, gmask, bboxes);

    k_mg<<<(FMAX + 127) / 128, 512, Lay<128>::SZ>>>(b3, b4);
    k_reduce<<<ROWS, 128>>>();
    k_q<<<(ROWS + 63) / 64, 256, Lay<64>::SZ>>>(tgt, gmask, b1, b2, b5, out);
}

// round 15
// speedup vs baseline: 1.7993x; 1.0334x over previous
#include <cuda_runtime.h>
#include <cuda_fp16.h>
#include <math.h>
#include <stdint.h>

#define BSZ 8
#define NQ 900
#define DD 256
#define KK 10
#define ROWS (BSZ*NQ)        /* 7200  */
#define FMAX (ROWS*KK)       /* 72000 */
#define WDIM 512

// ---------------- scratch (static __device__ arrays; no allocation) ----------
__device__ __align__(256) float4 g_pm[FMAX];
__device__ __align__(256) float  g_w[FMAX];
__device__ __align__(256) float  g_oval[FMAX];
__device__ __align__(256) float  g_mkval[FMAX];
__device__ __align__(256) __half g_feat[(size_t)FMAX*DD];   // fused MG output, fp16
__device__ int    g_rowbase[ROWS];
__device__ int    g_rowcnt[ROWS];
__device__ __align__(256) float  g_agg[(size_t)ROWS*DD];
__device__ float  g_s64[DD];
__device__ int    g_count;
// weights, [N][K] K-major rows, fp16. g_W3P = pair-summed W3 (K=256!)
__device__ __align__(256) __half g_W3P[DD*DD];
__device__ __align__(256) __half g_W1T[DD*DD];
__device__ __align__(256) __half g_W2T[DD*DD];
__device__ __align__(256) __half g_W4T[DD*DD];
__device__ __align__(256) __half g_W5T[DD*DD];

__device__ __forceinline__ void mma_f16(float* c, const uint32_t* a, const uint32_t* b) {
    asm volatile(
        "mma.sync.aligned.m16n8k16.row.col.f32.f16.f16.f32 "
        "{%0,%1,%2,%3}, {%4,%5,%6,%7}, {%8,%9}, {%0,%1,%2,%3};"
        : "+f"(c[0]), "+f"(c[1]), "+f"(c[2]), "+f"(c[3])
        : "r"(a[0]), "r"(a[1]), "r"(a[2]), "r"(a[3]), "r"(b[0]), "r"(b[1]));
}
__device__ __forceinline__ void ldsm4(uint32_t* r, uint32_t addr) {
    asm volatile("ldmatrix.sync.aligned.m8n8.x4.shared.b16 {%0,%1,%2,%3}, [%4];"
        : "=r"(r[0]), "=r"(r[1]), "=r"(r[2]), "=r"(r[3]) : "r"(addr));
}
__device__ __forceinline__ uint32_t smem_u32(const void* p) {
    uint32_t a;
    asm("{ .reg .u64 t; cvta.to.shared.u64 t, %1; cvt.u32.u64 %0, t; }" : "=r"(a) : "l"(p));
    return a;
}
__device__ __forceinline__ uint32_t packh2(float a, float b) {
    __half2 h = __floats2half2_rn(a, b);
    return *(uint32_t*)&h;
}
#define CP16(dst, src) asm volatile("cp.async.cg.shared.global [%0], [%1], 16;" :: "r"(dst), "l"(src))
#define CP_COMMIT()    asm volatile("cp.async.commit_group;" ::: "memory")
#define CP_WAIT0()     asm volatile("cp.async.wait_group 0;" ::: "memory")

#define HSTR 264       /* H-tile row stride, fp16 (odd 16B units) */

// ---------------- k_mg smem layout: BM=128, BK=64, PADH=72 ------------------
#define MGP   72
#define MG_SA   0
#define MG_SAB  (128*MGP*2)              /* 18432 */
#define MG_SB   (2*MG_SAB)               /* 36864 */
#define MG_SBB  (256*MGP*2)              /* 36864 */
#define MG_SH   (MG_SB + 2*MG_SBB)       /* 110592 */
#define MG_SHB  (128*HSTR*2)             /* 67584 */
#define MG_C0   (MG_SH + MG_SHB)         /* 178176 */
#define MG_C1   (MG_C0 + 1024)
#define MG_C2   (MG_C1 + 1024)
#define MG_PM   (MG_C2 + 1024)
#define MG_W    (MG_PM + 2048)
#define MG_CF   (MG_W + 512)
#define MG_SZ   (MG_CF + 256)            /* 184064 */

// ---------------- k_q smem layout: BM=64, BK=32, PADH=40 --------------------
#define QP    40
#define Q_SA    0
#define Q_SAB   (64*QP*2)                /* 5120 */
#define Q_SB    (2*Q_SAB)                /* 10240 */
#define Q_SBB   (256*QP*2)               /* 20480 */
#define Q_SH    (Q_SB + 2*Q_SBB)         /* 51200 */
#define Q_SHB   (64*HSTR*2)              /* 33792 */
#define Q_C0    (Q_SH + Q_SHB)           /* 84992 */
#define Q_C1    (Q_C0 + 1024)
#define Q_C2    (Q_C1 + 1024)
#define Q_SZ    (Q_C2 + 1024)            /* 88064 -> 2 CTAs/SM */

// ---------------- prep (merged): W3P + transposes + s64 + counter -----------
__global__ void k_prep(const float* __restrict__ W1, const float* __restrict__ W2,
                       const float* __restrict__ W3, const float* __restrict__ W4,
                       const float* __restrict__ W5) {
    int bid = blockIdx.x, tid = threadIdx.x;
    if (bid < 256) {
        int kp = bid, n = tid;
        int a = kp >> 7, sf = (kp >> 6) & 1, m = kp & 63;
        int j0 = a*256 + sf*128 + 2*m;
        float s = W3[(size_t)(64 + j0)*DD + n] + W3[(size_t)(65 + j0)*DD + n];
        g_W3P[n*DD + kp] = __float2half(s);
    } else if (bid < 1280) {
        int r = (bid - 256)*256 + tid;
        int mm = r >> 16, e = r & 65535;
        int n = e >> 8, k = e & 255;
        if      (mm == 0) g_W1T[e] = __float2half(W1[(size_t)k*DD + n]);
        else if (mm == 1) g_W2T[e] = __float2half(W2[(size_t)k*DD + n]);
        else if (mm == 2) g_W4T[e] = __float2half(W4[(size_t)k*DD + n]);
        else              g_W5T[e] = __float2half(W5[(size_t)k*DD + n]);
    } else {
        float s = 0.f;
        #pragma unroll 8
        for (int r = 0; r < 64; r++) s += W3[r*DD + tid];
        g_s64[tid] = s;
        if (tid == 0) g_count = 0;
    }
}

// ---------------- top-K: one warp per row, register-resident ----------------
#define NU 29
__global__ __launch_bounds__(256)
void k_topk(const float* __restrict__ ious,
            const float* __restrict__ gmask,
            const float* __restrict__ bboxes) {
    int wid = threadIdx.x >> 5, lid = threadIdx.x & 31;
    int r = blockIdx.x * 8 + wid;
    if (r >= ROWS) return;
    int b = r / NQ, i = r % NQ;
    const float* Mrow = gmask + b*NQ;
    float neg_i = 1.0f - Mrow[i];
    if (neg_i == 0.0f) {
        if (lid == 0) { g_rowbase[r] = 0; g_rowcnt[r] = 0; }
        return;
    }
    const float* irow = ious + (size_t)r * NQ;
    float ov[NU];
    #pragma unroll
    for (int u = 0; u < NU; u++) {
        int j = lid + u*32;
        ov[u] = (j < NQ) ? irow[j] * Mrow[j] * neg_i : -3.4e38f;
    }
    float kv[KK]; int ki[KK];
    float lastv = 3.5e38f; int lasti = -1;
    #pragma unroll
    for (int t = 0; t < KK; t++) {
        float lv = -3.4e38f; int li = NQ;
        #pragma unroll
        for (int u = 0; u < NU; u++) {
            int j = lid + u*32;
            float v = ov[u];
            bool inc = (v < lastv) || (v == lastv && j > lasti);
            if (inc && (v > lv || (v == lv && j < li))) { lv = v; li = j; }
        }
        #pragma unroll
        for (int off = 16; off > 0; off >>= 1) {
            float vv = __shfl_xor_sync(0xffffffffu, lv, off);
            int   ii = __shfl_xor_sync(0xffffffffu, li, off);
            if (vv > lv || (vv == lv && ii < li)) { lv = vv; li = ii; }
        }
        kv[t] = lv; ki[t] = li;
        lastv = lv; lasti = li;
    }
    if (lid == 0) {
        float mkv[KK];
        int cnt = 0;
        #pragma unroll
        for (int t = 0; t < KK; t++) {
            float nmk = Mrow[ki[t]];
            float mk  = (kv[t] >= 0.4f) ? nmk : 0.0f;
            mkv[t] = mk;
            if (mk != 0.0f) cnt++;
        }
        int base = (cnt > 0) ? atomicAdd(&g_count, cnt) : 0;
        g_rowbase[r] = base; g_rowcnt[r] = cnt;

        const float* cb = bboxes + (size_t)r * 4;
        float ccx = 0.5f*(cb[0]+cb[2]), ccy = 0.5f*(cb[1]+cb[3]);
        float cw = cb[2]-cb[0], ch = cb[3]-cb[1];
        int s = 0;
        #pragma unroll
        for (int t = 0; t < KK; t++) {
            if (mkv[t] == 0.0f) continue;
            const float* nb = bboxes + (size_t)(b*NQ + ki[t]) * 4;
            float dcx = 0.5f*(nb[0]+nb[2]) - ccx;
            float dcy = 0.5f*(nb[1]+nb[3]) - ccy;
            float dw  = (nb[2]-nb[0]) - cw;
            float dh  = (nb[3]-nb[1]) - ch;
            float4 pm;
            pm.x = logf(fmaxf(fabsf(dcx), 1e-7f));
            pm.y = logf(fmaxf(fabsf(dcy), 1e-7f));
            pm.z = logf(fmaxf(fabsf(dw ), 1e-7f));
            pm.w = logf(fmaxf(fabsf(dh ), 1e-7f));
            g_pm[base+s]    = pm;
            g_w[base+s]     = neg_i * Mrow[ki[t]] * mkv[t];
            g_oval[base+s]  = kv[t] * mkv[t];
            g_mkval[base+s] = mkv[t];
            s++;
        }
    }
}

// ---------------- common helpers --------------------------------------------
__device__ __forceinline__ void zero_acc(float acc[4][4][4]) {
    #pragma unroll
    for (int m = 0; m < 4; m++)
        #pragma unroll
        for (int n = 0; n < 4; n++)
            #pragma unroll
            for (int q = 0; q < 4; q++) acc[m][n][q] = 0.f;
}

// MMA over KB k-elements; A stride astr (runtime), B stride BSTR (template)
template<int KB, int BSTR>
__device__ __forceinline__ void mma_chunk(uint32_t aab, uint32_t bbb, int astr,
                                          float acc[4][4][4]) {
    #pragma unroll
    for (int kb = 0; kb < KB; kb += 16) {
        uint32_t af[4][4], bq[2][4];
        #pragma unroll
        for (int m = 0; m < 4; m++)
            ldsm4(af[m], aab + (uint32_t)((m*16*astr + kb) * 2));
        #pragma unroll
        for (int g = 0; g < 2; g++)
            ldsm4(bq[g], bbb + (uint32_t)((g*16*BSTR + kb) * 2));
        #pragma unroll
        for (int m = 0; m < 4; m++) {
            #pragma unroll
            for (int n = 0; n < 4; n++) {
                uint32_t bfr[2] = { bq[n>>1][n&1], bq[n>>1][(n&1)+2] };
                mma_f16(acc[m][n], af[m], bfr);
            }
        }
    }
}

// ---------------- fused MG: H = relu(wave_half@W3P+...); feat = H@W4 --------
// BM=128, BK=64, 512 threads, warps 2M x 8N (tile 64x32)
__global__ __launch_bounds__(512, 1)
void k_mg(const float* __restrict__ b3, const float* __restrict__ b4) {
    extern __shared__ __align__(16) char smem[];
    float*  bias3_s = (float*)(smem + MG_C0);
    float*  s64_s   = (float*)(smem + MG_C1);
    float*  bias4_s = (float*)(smem + MG_C2);
    float4* pm_s    = (float4*)(smem + MG_PM);
    float*  w_s     = (float*)(smem + MG_W);
    float*  coef_s  = (float*)(smem + MG_CF);

    int M = g_count;
    int m0 = blockIdx.x * 128;
    if (m0 >= M) return;

    int tid = threadIdx.x, wid = tid >> 5, lid = tid & 31;
    int gid = lid >> 2, ti = lid & 3;
    int warpM = wid & 1, warpN = wid >> 1;
    int l16 = lid & 15, lk = (lid >> 4) * 8;

    if (tid < 256) { bias3_s[tid] = b3[tid]; s64_s[tid] = g_s64[tid]; bias4_s[tid] = b4[tid]; }
    else if (tid < 384) {
        int rr = m0 + tid - 256;
        if (rr < M) { pm_s[tid-256] = g_pm[rr]; w_s[tid-256] = g_w[rr]; }
        else { pm_s[tid-256] = make_float4(0.f,0.f,0.f,0.f); w_s[tid-256] = 0.f; }
    } else if (tid < 448) {
        coef_s[tid-384] = 6.2831853071795865f *
                          exp2f(-(float)(tid-384) * (13.287712379549450f/64.f));
    }
    __syncthreads();

    uint32_t Asm_b = smem_u32(smem + MG_SA);
    uint32_t Bsm_b = smem_u32(smem + MG_SB);
    uint32_t Hsm_b = smem_u32(smem + MG_SH);
    uint32_t aaddr = Asm_b + (uint32_t)((warpM*64 + l16) * MGP + lk) * 2u;
    uint32_t baddr = Bsm_b + (uint32_t)((warpN*32 + l16) * MGP + lk) * 2u;
    uint32_t haddr = Hsm_b + (uint32_t)((warpM*64 + l16) * HSTR + lk) * 2u;

    float acc[4][4][4];
    const int s_row = tid >> 2, s_q = tid & 3;

    // B chunk issue: 256 rows x 64 halves = 2048 x 16B, 4 per thread
    auto issueB = [&](const __half* WT, int c, int buf) {
        #pragma unroll
        for (int i = 0; i < 4; i++) {
            int f = tid + i*512;
            int row = f >> 3, q = f & 7;
            uint32_t dst = Bsm_b + buf*MG_SBB + (uint32_t)(row*MGP*2 + q*16);
            CP16(dst, WT + (size_t)row*DD + c*64 + q*8);
        }
    };
    // wave fill for 32-wide sub-chunk c32: 8 halves at k = c32*32 + s_q*8
    float4 pmv = pm_s[s_row]; float wv = w_s[s_row];
    auto fill = [&](int c32) -> uint4 {
        const float* pmp = (const float*)&pmv;
        uint32_t h[4];
        #pragma unroll
        for (int p = 0; p < 4; p++) {
            float v[2];
            #pragma unroll
            for (int e = 0; e < 2; e++) {
                int k = c32*32 + s_q*8 + 2*p + e;
                int a = k >> 7, sf = (k >> 6) & 1, m = k & 63;
                float ang = coef_s[m] * pmp[2*a + sf];
                v[e] = (sf ? __cosf(ang) : __sinf(ang)) * wv;
            }
            h[p] = packh2(v[0], v[1]);
        }
        return make_uint4(h[0], h[1], h[2], h[3]);
    };
    auto storeA = [&](int buf, uint4 v0, uint4 v1) {
        char* base = smem + MG_SA + buf*MG_SAB + (s_row*MGP)*2;
        *(uint4*)(base + s_q*16)        = v0;
        *(uint4*)(base + 64 + s_q*16)   = v1;   // k offset +32 halves
    };

    // ---- phase 1: wave_half @ W3P (K=256, 4 chunks of 64) ----
    zero_acc(acc);
    issueB(g_W3P, 0, 0); CP_COMMIT();
    storeA(0, fill(0), fill(1));
    CP_WAIT0(); __syncthreads();
    for (int c = 0; c < 4; c++) {
        int buf = c & 1;
        bool pf = (c + 1 < 4);
        uint4 nv0, nv1;
        if (pf) { issueB(g_W3P, c+1, buf^1); CP_COMMIT(); nv0 = fill(2*c+2); nv1 = fill(2*c+3); }
        mma_chunk<64, MGP>(aaddr + buf*MG_SAB, baddr + buf*MG_SBB, MGP, acc);
        if (pf) { storeA(buf^1, nv0, nv1); CP_WAIT0(); }
        __syncthreads();
    }

    // ---- epilogue 1: H into Hsm (fp16) ----
    __half* Hsm = (__half*)(smem + MG_SH);
    #pragma unroll
    for (int m = 0; m < 4; m++) {
        int rl0 = warpM*64 + m*16 + gid;
        #pragma unroll
        for (int h = 0; h < 2; h++) {
            int rl = rl0 + h*8;
            int rg = m0 + rl;
            float ovl = (rg < M) ? g_oval[rg] : 0.f;
            #pragma unroll
            for (int n = 0; n < 4; n++) {
                int lc = warpN*32 + n*8 + ti*2;
                float v0 = fmaxf(acc[m][n][h*2+0] + bias3_s[lc]   + ovl*s64_s[lc],   0.f);
                float v1 = fmaxf(acc[m][n][h*2+1] + bias3_s[lc+1] + ovl*s64_s[lc+1], 0.f);
                *(__half2*)(Hsm + rl*HSTR + lc) = __floats2half2_rn(v0, v1);
            }
        }
    }
    __syncthreads();

    // ---- phase 2: H @ W4T (K=256, 4 chunks of 64) ----
    zero_acc(acc);
    issueB(g_W4T, 0, 0); CP_COMMIT();
    CP_WAIT0(); __syncthreads();
    for (int c = 0; c < 4; c++) {
        int buf = c & 1;
        bool pf = (c + 1 < 4);
        if (pf) { issueB(g_W4T, c+1, buf^1); CP_COMMIT(); }
        mma_chunk<64, MGP>(haddr + (uint32_t)(c*64*2), baddr + buf*MG_SBB, HSTR, acc);
        if (pf) { CP_WAIT0(); }
        __syncthreads();
    }

    // ---- epilogue 2: feat (fp16) to global ----
    #pragma unroll
    for (int m = 0; m < 4; m++) {
        int rl0 = warpM*64 + m*16 + gid;
        #pragma unroll
        for (int h = 0; h < 2; h++) {
            int rg = m0 + rl0 + h*8;
            if (rg >= M) continue;
            #pragma unroll
            for (int n = 0; n < 4; n++) {
                int lc = warpN*32 + n*8 + ti*2;
                float v0 = acc[m][n][h*2+0] + bias4_s[lc];
                float v1 = acc[m][n][h*2+1] + bias4_s[lc+1];
                *(__half2*)(g_feat + (size_t)rg*DD + lc) = __floats2half2_rn(v0, v1);
            }
        }
    }
}

// ---------------- masked max over K neighbors (fp16 feat, half2 lanes) ------
__global__ __launch_bounds__(128)
void k_reduce() {
    int r = blockIdx.x, d = threadIdx.x;
    int base = g_rowbase[r], cnt = g_rowcnt[r];
    float floorv = (cnt < KK) ? 0.0f : -3.4e38f;
    float m0 = floorv, m1 = floorv;
    for (int e = 0; e < cnt; e++) {
        float mk = g_mkval[base+e];
        __half2 hv = *(const __half2*)(g_feat + (size_t)(base+e)*DD + 2*d);
        float2 fv = __half22float2(hv);
        m0 = fmaxf(m0, mk * fv.x);
        m1 = fmaxf(m1, mk * fv.y);
    }
    *(float2*)(g_agg + (size_t)r*DD + 2*d) = make_float2(m0, m1);
}

// ---------------- fused query chain: T1 -> Z -> out (BM=64, BK=32) ----------
__global__ __launch_bounds__(256, 2)
void k_q(const float* __restrict__ tgt, const float* __restrict__ gmask,
         const float* __restrict__ b1, const float* __restrict__ b2,
         const float* __restrict__ b5, float* __restrict__ out) {
    extern __shared__ __align__(16) char smem[];
    float* bias1_s = (float*)(smem + Q_C0);
    float* bias2_s = (float*)(smem + Q_C1);
    float* bias5_s = (float*)(smem + Q_C2);

    const int M = ROWS;
    int m0 = blockIdx.x * 64;
    if (m0 >= M) return;

    int tid = threadIdx.x, wid = tid >> 5, lid = tid & 31;
    int gid = lid >> 2, ti = lid & 3;
    int warpN = wid;
    int l16 = lid & 15, lk = (lid >> 4) * 8;

    bias1_s[tid] = b1[tid]; bias2_s[tid] = b2[tid]; bias5_s[tid] = b5[tid];
    __syncthreads();

    uint32_t Asm_b = smem_u32(smem + Q_SA);
    uint32_t Bsm_b = smem_u32(smem + Q_SB);
    uint32_t Hsm_b = smem_u32(smem + Q_SH);
    uint32_t aaddr = Asm_b + (uint32_t)(l16 * QP + lk) * 2u;
    uint32_t baddr = Bsm_b + (uint32_t)((warpN*32 + l16) * QP + lk) * 2u;
    uint32_t haddr = Hsm_b + (uint32_t)(l16 * HSTR + lk) * 2u;
    __half* Hsm = (__half*)(smem + Q_SH);

    float acc[4][4][4];
    const int s_row = tid >> 2, s_q = tid & 3;

    auto issueB = [&](const __half* WT, int c, int buf) {
        #pragma unroll
        for (int i = 0; i < 4; i++) {
            int f = tid + i*256;
            int row = f >> 2, q = f & 3;
            uint32_t dst = Bsm_b + buf*Q_SBB + (uint32_t)(row*QP*2 + q*16);
            CP16(dst, WT + (size_t)row*DD + c*32 + q*8);
        }
    };

    // ---- phase 1: relu(tgt @ W1T + b1) -> Hsm ----
    zero_acc(acc);
    {
        auto fill = [&](int c) -> uint4 {
            int gr = m0 + s_row;
            float4 f0 = make_float4(0.f,0.f,0.f,0.f), f1 = f0;
            if (gr < M) {
                const float* ap = tgt + (size_t)gr*DD + c*32 + s_q*8;
                f0 = *(const float4*)ap; f1 = *(const float4*)(ap + 4);
            }
            return make_uint4(packh2(f0.x,f0.y), packh2(f0.z,f0.w),
                              packh2(f1.x,f1.y), packh2(f1.z,f1.w));
        };
        auto storeA = [&](int buf, uint4 v) {
            *(uint4*)(smem + Q_SA + buf*Q_SAB + (s_row*QP + s_q*8)*2) = v;
        };
        issueB(g_W1T, 0, 0); CP_COMMIT();
        storeA(0, fill(0));
        CP_WAIT0(); __syncthreads();
        for (int c = 0; c < 8; c++) {
            int buf = c & 1;
            bool pf = (c + 1 < 8);
            uint4 nv;
            if (pf) { issueB(g_W1T, c+1, buf^1); CP_COMMIT(); nv = fill(c+1); }
            mma_chunk<32, QP>(aaddr + buf*Q_SAB, baddr + buf*Q_SBB, QP, acc);
            if (pf) { storeA(buf^1, nv); CP_WAIT0(); }
            __syncthreads();
        }
    }
    #pragma unroll
    for (int m = 0; m < 4; m++) {
        int rl0 = m*16 + gid;
        #pragma unroll
        for (int h = 0; h < 2; h++) {
            int rl = rl0 + h*8;
            #pragma unroll
            for (int n = 0; n < 4; n++) {
                int lc = warpN*32 + n*8 + ti*2;
                float v0 = fmaxf(acc[m][n][h*2+0] + bias1_s[lc],   0.f);
                float v1 = fmaxf(acc[m][n][h*2+1] + bias1_s[lc+1], 0.f);
                *(__half2*)(Hsm + rl*HSTR + lc) = __floats2half2_rn(v0, v1);
            }
        }
    }
    __syncthreads();

    // ---- phase 2: Z = (T1 @ W2T + b2)*neg + agg -> Hsm ----
    zero_acc(acc);
    issueB(g_W2T, 0, 0); CP_COMMIT();
    CP_WAIT0(); __syncthreads();
    for (int c = 0; c < 8; c++) {
        int buf = c & 1;
        bool pf = (c + 1 < 8);
        if (pf) { issueB(g_W2T, c+1, buf^1); CP_COMMIT(); }
        mma_chunk<32, QP>(haddr + (uint32_t)(c*32*2), baddr + buf*Q_SBB, HSTR, acc);
        if (pf) { CP_WAIT0(); }
        __syncthreads();
    }
    #pragma unroll
    for (int m = 0; m < 4; m++) {
        int rl0 = m*16 + gid;
        #pragma unroll
        for (int h = 0; h < 2; h++) {
            int rl = rl0 + h*8;
            int rg = m0 + rl;
            if (rg >= M) continue;
            float ng = 1.f - gmask[rg];
            const float* ar = g_agg + (size_t)rg*DD;
            #pragma unroll
            for (int n = 0; n < 4; n++) {
                int lc = warpN*32 + n*8 + ti*2;
                float v0 = (acc[m][n][h*2+0] + bias2_s[lc])   * ng + ar[lc];
                float v1 = (acc[m][n][h*2+1] + bias2_s[lc+1]) * ng + ar[lc+1];
                *(__half2*)(Hsm + rl*HSTR + lc) = __floats2half2_rn(v0, v1);
            }
        }
    }
    __syncthreads();

    // ---- phase 3: out = relu(Z @ W5T + b5) * neg ----
    zero_acc(acc);
    issueB(g_W5T, 0, 0); CP_COMMIT();
    CP_WAIT0(); __syncthreads();
    for (int c = 0; c < 8; c++) {
        int buf = c & 1;
        bool pf = (c + 1 < 8);
        if (pf) { issueB(g_W5T, c+1, buf^1); CP_COMMIT(); }
        mma_chunk<32, QP>(haddr + (uint32_t)(c*32*2), baddr + buf*Q_SBB, HSTR, acc);
        if (pf) { CP_WAIT0(); }
        __syncthreads();
    }
    #pragma unroll
    for (int m = 0; m < 4; m++) {
        int rl0 = m*16 + gid;
        #pragma unroll
        for (int h = 0; h < 2; h++) {
            int rg = m0 + rl0 + h*8;
            if (rg >= M) continue;
            float ng = 1.f - gmask[rg];
            #pragma unroll
            for (int n = 0; n < 4; n++) {
                int lc = warpN*32 + n*8 + ti*2;
                float v0 = fmaxf(acc[m][n][h*2+0] + bias5_s[lc],   0.f) * ng;
                float v1 = fmaxf(acc[m][n][h*2+1] + bias5_s[lc+1], 0.f) * ng;
                *(float2*)(out + (size_t)rg*DD + lc) = make_float2(v0, v1);
            }
        }
    }
}

// ---------------- launch ----------------------------------------------------
extern "C" void kernel_launch(void* const* d_in, const int* in_sizes, int n_in,
                              void* d_out, int out_size) {
    const float* tgt    = (const float*)d_in[0];
    const float* ious   = (const float*)d_in[1];
    const float* bboxes = (const float*)d_in[2];
    const float* gmask  = (const float*)d_in[3];
    const float* W1 = (const float*)d_in[4];  const float* b1 = (const float*)d_in[5];
    const float* W2 = (const float*)d_in[6];  const float* b2 = (const float*)d_in[7];
    const float* W3 = (const float*)d_in[8];  const float* b3 = (const float*)d_in[9];
    const float* W4 = (const float*)d_in[10]; const float* b4 = (const float*)d_in[11];
    const float* W5 = (const float*)d_in[12]; const float* b5 = (const float*)d_in[13];
    float* out = (float*)d_out;

    cudaFuncSetAttribute(k_mg, cudaFuncAttributeMaxDynamicSharedMemorySize, MG_SZ);
    cudaFuncSetAttribute(k_q,  cudaFuncAttributeMaxDynamicSharedMemorySize, Q_SZ);

    k_prep<<<1281, 256>>>(W1, W2, W3, W4, W5);
    k_topk<<<(ROWS + 7) / 8, 256>>>(ious, gmask, bboxes);

    k_mg<<<(FMAX + 127) / 128, 512, MG_SZ>>>(b3, b4);
    k_reduce<<<ROWS, 128>>>();
    k_q<<<(ROWS + 63) / 64, 256, Q_SZ>>>(tgt, gmask, b1, b2, b5, out);
}